// round 12
// baseline (speedup 1.0000x reference)
#include <cuda_runtime.h>
#include <math.h>

// Problem constants
#define B_  2048
#define T_  512
#define F_  32
#define H_  128
#define BT  14       // batch rows per CTA -> 147 CTAs = one wave on 148 SMs
#define NT  512      // 128 j x 2 ksplit x 2 batch-half
#define BST 15       // zbuf batch stride (ull)
#define HS2 65       // h row stride in ulonglong2 (64 kk + 1 pad)
#define XS2 17       // x row stride in ulonglong2 (16 kk + 1 pad)
#define CW  8        // Whh0 2k-rows cached in SMEM (of 64)

typedef unsigned long long ull;

// Gate-pair interleaved weights: entry [r*256 + p*128 + j] is ulonglong2
//   .x = {W[gA][2r],   W[gB][2r]}     .y = {W[gA][2r+1], W[gB][2r+1]}
// pair p=0: (gA,gB) = (i_j, f_j) = (j, 128+j); p=1: (g_j, o_j) = (256+j, 384+j).
// +2 pad rows for the distance-2 prefetch (device globals are zero-init).
__device__ ulonglong2 g_Wih0p[(16 + 2) * 256];
__device__ ulonglong2 g_Whh0p[(64 + 2) * 256];
__device__ ulonglong2 g_Wih1p[(64 + 2) * 256];
__device__ ulonglong2 g_Whh1p[(64 + 2) * 256];

__device__ __forceinline__ ull pack2d(float lo, float hi) {
    return (ull)__float_as_uint(lo) | ((ull)__float_as_uint(hi) << 32);
}

__global__ void prep(const float* __restrict__ Wih0,
                     const float* __restrict__ Whh0,
                     const float* __restrict__ Wih1,
                     const float* __restrict__ Whh1) {
    int idx = blockIdx.x * blockDim.x + threadIdx.x;  // 0..16383
    int col = idx & 255, r = idx >> 8;                // r = 2k-row 0..63
    int p = col >> 7, j = col & 127;
    int gA = p ? 256 + j : j;
    int gB = p ? 384 + j : 128 + j;
    int k = 2 * r;
    ulonglong2 e;
    e.x = pack2d(Whh0[gA * 128 + k],     Whh0[gB * 128 + k]);
    e.y = pack2d(Whh0[gA * 128 + k + 1], Whh0[gB * 128 + k + 1]);
    g_Whh0p[idx] = e;
    e.x = pack2d(Wih1[gA * 128 + k],     Wih1[gB * 128 + k]);
    e.y = pack2d(Wih1[gA * 128 + k + 1], Wih1[gB * 128 + k + 1]);
    g_Wih1p[idx] = e;
    e.x = pack2d(Whh1[gA * 128 + k],     Whh1[gB * 128 + k]);
    e.y = pack2d(Whh1[gA * 128 + k + 1], Whh1[gB * 128 + k + 1]);
    g_Whh1p[idx] = e;
    if (r < 16) {
        e.x = pack2d(Wih0[gA * 32 + k],     Wih0[gB * 32 + k]);
        e.y = pack2d(Wih0[gA * 32 + k + 1], Wih0[gB * 32 + k + 1]);
        g_Wih0p[idx] = e;
    }
}

__device__ __forceinline__ ull ffma2(ull a, ull b, ull c) {
    ull d;
    asm("fma.rn.f32x2 %0, %1, %2, %3;" : "=l"(d) : "l"(a), "l"(b), "l"(c));
    return d;
}
__device__ __forceinline__ ull addx2(ull a, ull b) {
    ull r;
    asm("add.rn.f32x2 %0, %1, %2;" : "=l"(r) : "l"(a), "l"(b));
    return r;
}
__device__ __forceinline__ ull dup2(float w) {
    ull d;
    asm("mov.b64 %0, {%1, %1};" : "=l"(d) : "f"(w));
    return d;
}
__device__ __forceinline__ float2 u2f(ull v) {
    float2 r;
    asm("mov.b64 {%0, %1}, %2;" : "=f"(r.x), "=f"(r.y) : "l"(v));
    return r;
}
__device__ __forceinline__ float sigm(float x) {
    return 1.0f / (1.0f + __expf(-x));
}
__device__ __forceinline__ float tanh_f(float x) {
    float e = __expf(-2.0f * fabsf(x));
    float t = (1.0f - e) / (1.0f + e);
    return x >= 0.0f ? t : -t;
}

// One 2k-iteration: 2 gate-pairs x 7 batches. hb points at this half's batch-0
// row of the dup'd activation array; hv = {hdup[2kk], hdup[2kk+1]}.
__device__ __forceinline__ void iter2k(ulonglong2 wA, ulonglong2 wB,
                                       const ulonglong2* __restrict__ hb,
                                       int stride, int kk,
                                       ull zA[7], ull zB[7]) {
#pragma unroll
    for (int b = 0; b < 7; ++b) {
        ulonglong2 hv = hb[b * stride + kk];
        zA[b] = ffma2(hv.x, wA.x, zA[b]);
        zA[b] = ffma2(hv.y, wA.y, zA[b]);
        zB[b] = ffma2(hv.x, wB.x, zB[b]);
        zB[b] = ffma2(hv.y, wB.y, zB[b]);
    }
}

// Streamed panel: Wt already offset to (kbase row, pair 0, j); pair 1 at +128;
// row stride 256. Distance-2 rolling prefetch (+2 pad rows exist).
template <int KG>
__device__ __forceinline__ void panel_g(const ulonglong2* __restrict__ Wt,
                                        const ulonglong2* __restrict__ hb,
                                        int stride, int kk0,
                                        ull zA[7], ull zB[7]) {
    ulonglong2 a0 = Wt[0], b0 = Wt[128], a1 = Wt[256], b1 = Wt[256 + 128];
#pragma unroll 1
    for (int r = 0; r < KG; ++r) {
        ulonglong2 an = Wt[(size_t)(r + 2) * 256];
        ulonglong2 bn = Wt[(size_t)(r + 2) * 256 + 128];
        iter2k(a0, b0, hb, stride, kk0 + r, zA, zB);
        a0 = a1; a1 = an;
        b0 = b1; b1 = bn;
    }
}

// Cached panel (weights in SMEM).
template <int KG>
__device__ __forceinline__ void panel_s(const ulonglong2* __restrict__ Ws,
                                        const ulonglong2* __restrict__ hb,
                                        int stride, int kk0,
                                        ull zA[7], ull zB[7]) {
#pragma unroll 1
    for (int r = 0; r < KG; ++r) {
        ulonglong2 wa = Ws[r * 256];
        ulonglong2 wb = Ws[r * 256 + 128];
        iter2k(wa, wb, hb, stride, kk0 + r, zA, zB);
    }
}

extern __shared__ ulonglong2 smemU[];

__global__ void __launch_bounds__(NT, 1)
lstm_persistent(const float* __restrict__ x,
                const float* __restrict__ b0,
                const float* __restrict__ b1,
                const float* __restrict__ Wfc,
                const float* __restrict__ bfc,
                float* __restrict__ out) {
    // SMEM layout
    ulonglong2* sWih0 = smemU;                 // 16*256
    ulonglong2* sWhh0 = smemU + 16 * 256;      // CW*256
    float* sb0 = (float*)(smemU + (16 + CW) * 256);   // 512
    float* sb1 = sb0 + 512;                           // 512
    ulonglong2* h0d = (ulonglong2*)(sb1 + 512);       // 14*HS2
    ulonglong2* h1d = h0d + BT * HS2;
    float* c0 = (float*)(h1d + BT * HS2);             // 1792
    float* c1 = c0 + BT * H_;                          // 1792
    ull* zbu0 = (ull*)(c1 + BT * H_);                  // 256*BST
    ull* zbu1 = zbu0 + 256 * BST;
    ulonglong2* xd0 = (ulonglong2*)(zbu1 + 256 * BST); // 14*XS2
    ulonglong2* xd1 = xd0 + BT * XS2;

    const int tid = threadIdx.x;
    const int j = tid & 127;
    const int ks = (tid >> 7) & 1;
    const int half = tid >> 8;
    const int bo = half * 7;                   // batch-row offset
    const int b_base = blockIdx.x * BT;
    const int nb = min(BT, B_ - b_base);
    ull* zmy = ks ? zbu1 : zbu0;

    // one-time fills
    for (int i = tid; i < 16 * 256; i += NT) sWih0[i] = g_Wih0p[i];
    for (int i = tid; i < CW * 256; i += NT) sWhh0[i] = g_Whh0p[i];
    if (tid < 512) { sb0[tid] = b0[tid]; sb1[tid] = b1[tid]; }
    for (int i = tid; i < 2 * BT * HS2; i += NT)
        h0d[i] = make_ulonglong2(0ull, 0ull);
    for (int i = tid; i < 2 * BT * H_; i += NT) c0[i] = 0.0f;
    // stage x(t=0), duplicated per value
    for (int i = tid; i < BT * F_; i += NT) {
        int b = i / F_, f = i % F_;
        float v = (b < nb) ? x[((size_t)(b_base + b) * T_) * F_ + f] : 0.0f;
        ((ull*)xd0)[b * (2 * XS2) + f] = dup2(v);
    }
    __syncthreads();

    ulonglong2* xb[2] = { xd0, xd1 };
    int cur = 0;
    for (int t = 0; t < T_; ++t) {
        // ---------- layer 0 GEMM ----------
        ull zA[7], zB[7];
#pragma unroll
        for (int b = 0; b < 7; ++b) { zA[b] = 0ull; zB[b] = 0ull; }
        {
            const ulonglong2* xh = xb[cur] + bo * XS2;
            const ulonglong2* h0h = h0d + bo * HS2;
            if (ks == 0) {
                panel_s<8>(sWih0 + j, xh, XS2, 0, zA, zB);
                panel_s<CW>(sWhh0 + j, h0h, HS2, 0, zA, zB);
                panel_g<32 - CW>(g_Whh0p + CW * 256 + j, h0h, HS2, CW, zA, zB);
            } else {
                panel_s<8>(sWih0 + 8 * 256 + j, xh, XS2, 8, zA, zB);
                panel_g<32>(g_Whh0p + 32 * 256 + j, h0h, HS2, 32, zA, zB);
            }
        }
#pragma unroll
        for (int b = 0; b < 7; ++b) {
            zmy[j * BST + bo + b] = zA[b];
            zmy[(128 + j) * BST + bo + b] = zB[b];
        }
        __syncthreads();

        // ---------- layer 0 gate update ----------
        for (int i = tid; i < BT * H_; i += NT) {
            int b = i >> 7, j2 = i & 127;
            float2 zif = u2f(addx2(zbu0[j2 * BST + b], zbu1[j2 * BST + b]));
            float2 zgo = u2f(addx2(zbu0[(128 + j2) * BST + b],
                                   zbu1[(128 + j2) * BST + b]));
            float zi = zif.x + sb0[j2];
            float zf = zif.y + sb0[128 + j2];
            float zg = zgo.x + sb0[256 + j2];
            float zo = zgo.y + sb0[384 + j2];
            float c = c0[i];
            float nc = sigm(zf) * c + sigm(zi) * tanh_f(zg);
            c0[i] = nc;
            ((ull*)h0d)[b * (2 * HS2) + j2] = dup2(sigm(zo) * tanh_f(nc));
        }
        __syncthreads();

        // ---------- layer 1 GEMM ----------
#pragma unroll
        for (int b = 0; b < 7; ++b) { zA[b] = 0ull; zB[b] = 0ull; }
        {
            const ulonglong2* h0h = h0d + bo * HS2;
            const ulonglong2* h1h = h1d + bo * HS2;
            if (ks == 0) {
                panel_g<32>(g_Wih1p + j, h0h, HS2, 0, zA, zB);
                panel_g<32>(g_Whh1p + j, h1h, HS2, 0, zA, zB);
            } else {
                panel_g<32>(g_Wih1p + 32 * 256 + j, h0h, HS2, 32, zA, zB);
                panel_g<32>(g_Whh1p + 32 * 256 + j, h1h, HS2, 32, zA, zB);
            }
        }
#pragma unroll
        for (int b = 0; b < 7; ++b) {
            zmy[j * BST + bo + b] = zA[b];
            zmy[(128 + j) * BST + bo + b] = zB[b];
        }
        // stage x(t+1) while z settles
        if (t + 1 < T_) {
            for (int i = tid; i < BT * F_; i += NT) {
                int b = i / F_, f = i % F_;
                float v = (b < nb)
                    ? x[((size_t)(b_base + b) * T_ + (t + 1)) * F_ + f]
                    : 0.0f;
                ((ull*)xb[cur ^ 1])[b * (2 * XS2) + f] = dup2(v);
            }
        }
        __syncthreads();

        // ---------- layer 1 gate update ----------
        for (int i = tid; i < BT * H_; i += NT) {
            int b = i >> 7, j2 = i & 127;
            float2 zif = u2f(addx2(zbu0[j2 * BST + b], zbu1[j2 * BST + b]));
            float2 zgo = u2f(addx2(zbu0[(128 + j2) * BST + b],
                                   zbu1[(128 + j2) * BST + b]));
            float zi = zif.x + sb1[j2];
            float zf = zif.y + sb1[128 + j2];
            float zg = zgo.x + sb1[256 + j2];
            float zo = zgo.y + sb1[384 + j2];
            float c = c1[i];
            float nc = sigm(zf) * c + sigm(zi) * tanh_f(zg);
            c1[i] = nc;
            ((ull*)h1d)[b * (2 * HS2) + j2] = dup2(sigm(zo) * tanh_f(nc));
        }
        __syncthreads();
        cur ^= 1;
    }

    // FC head: h1d holds final h (dup'd); read the low lane.
    if (tid < nb) {
        const float2* hf = (const float2*)(h1d + (size_t)tid * HS2);
        float s = bfc[0];
#pragma unroll
        for (int k = 0; k < H_; ++k) s = fmaf(hf[k].x, Wfc[k], s);
        out[b_base + tid] = s;
    }
}

extern "C" void kernel_launch(void* const* d_in, const int* in_sizes, int n_in,
                              void* d_out, int out_size) {
    const float* x    = (const float*)d_in[0];
    const float* Wih0 = (const float*)d_in[1];
    const float* Whh0 = (const float*)d_in[2];
    const float* b0   = (const float*)d_in[3];
    const float* Wih1 = (const float*)d_in[4];
    const float* Whh1 = (const float*)d_in[5];
    const float* b1   = (const float*)d_in[6];
    const float* Wfc  = (const float*)d_in[7];
    const float* bfc  = (const float*)d_in[8];
    float* out = (float*)d_out;
    (void)in_sizes; (void)n_in; (void)out_size;

    prep<<<64, 256>>>(Wih0, Whh0, Wih1, Whh1);

    const int smem_bytes =
        (16 + CW) * 256 * (int)sizeof(ulonglong2) +  // weight caches
        2 * 512 * (int)sizeof(float) +               // biases
        2 * BT * HS2 * (int)sizeof(ulonglong2) +     // dup'd h (2 layers)
        2 * BT * H_ * (int)sizeof(float) +           // c (2 layers)
        2 * 256 * BST * (int)sizeof(ull) +           // split-K zbufs
        2 * BT * XS2 * (int)sizeof(ulonglong2);      // dup'd x double buffer
    cudaFuncSetAttribute(lstm_persistent,
                         cudaFuncAttributeMaxDynamicSharedMemorySize,
                         smem_bytes);

    lstm_persistent<<<(B_ + BT - 1) / BT, NT, smem_bytes>>>(
        x, b0, b1, Wfc, bfc, out);
}

// round 13
// speedup vs baseline: 1.3039x; 1.3039x over previous
#include <cuda_runtime.h>
#include <math.h>

// Problem constants
#define B_  2048
#define T_  512
#define F_  32
#define H_  128
#define BT  14       // batch rows per CTA -> 147 CTAs = one wave on 148 SMs
#define P_  7        // batch pairs per CTA
#define NT  512      // (half: pairs 0-3 / 4-6) x (ksplit: lo/hi K) x 128 j
#define PST 9        // zbuf stride in ull per gate row
#define CWHH 5       // Whh0 kg-rows cached in SMEM (of 32)

typedef unsigned long long ull;

// Weights laid out [kg][gt][j] float4 (4 consecutive k per load):
// index = (kg*4 + gt)*128 + j ; gate = gt*128 + j ; k = 4*kg.
// Lanes (consecutive j) are fully coalesced. +2 kg rows pad for prefetch.
__device__ float4 g_Wih0p[(8 + 2) * 512];
__device__ float4 g_Whh0p[(32 + 2) * 512];
__device__ float4 g_Wih1p[(32 + 2) * 512];
__device__ float4 g_Whh1p[(32 + 2) * 512];

__global__ void prep(const float* __restrict__ Wih0,
                     const float* __restrict__ Whh0,
                     const float* __restrict__ Wih1,
                     const float* __restrict__ Whh1) {
    int idx = blockIdx.x * blockDim.x + threadIdx.x;  // 0..16383
    int j = idx & 127, gt = (idx >> 7) & 3, kg = idx >> 9;
    int gate = gt * 128 + j;
    g_Whh0p[idx] = *(const float4*)(Whh0 + gate * 128 + 4 * kg);
    g_Wih1p[idx] = *(const float4*)(Wih1 + gate * 128 + 4 * kg);
    g_Whh1p[idx] = *(const float4*)(Whh1 + gate * 128 + 4 * kg);
    if (kg < 8)
        g_Wih0p[idx] = *(const float4*)(Wih0 + gate * 32 + 4 * kg);
}

__device__ __forceinline__ ull ffma2(ull a, ull b, ull c) {
    ull d;
    asm("fma.rn.f32x2 %0, %1, %2, %3;" : "=l"(d) : "l"(a), "l"(b), "l"(c));
    return d;
}
__device__ __forceinline__ ull dup2(float w) {
    ull d;
    asm("mov.b64 %0, {%1, %1};" : "=l"(d) : "f"(w));
    return d;
}
__device__ __forceinline__ float2 u2f(ull v) {
    float2 r;
    asm("mov.b64 {%0, %1}, %2;" : "=f"(r.x), "=f"(r.y) : "l"(v));
    return r;
}
__device__ __forceinline__ float sigm(float x) {
    return 1.0f / (1.0f + __expf(-x));
}
__device__ __forceinline__ float tanh_f(float x) {
    float e = __expf(-2.0f * fabsf(x));
    float t = (1.0f - e) / (1.0f + e);
    return x >= 0.0f ? t : -t;
}

// 2 k-values, 4 gates, NP pairs. kp = 16B index into each pair's h row.
template <int KDIM, int NP>
__device__ __forceinline__ void k2body(float2 w0, float2 w1, float2 w2, float2 w3,
                                       const float2* __restrict__ hp,
                                       ull z[4][NP], int kp) {
    ull d00 = dup2(w0.x), d01 = dup2(w0.y);
    ull d10 = dup2(w1.x), d11 = dup2(w1.y);
    ull d20 = dup2(w2.x), d21 = dup2(w2.y);
    ull d30 = dup2(w3.x), d31 = dup2(w3.y);
#pragma unroll
    for (int p = 0; p < NP; ++p) {
        ulonglong2 v = ((const ulonglong2*)(hp + p * KDIM))[kp];
        z[0][p] = ffma2(v.y, d01, ffma2(v.x, d00, z[0][p]));
        z[1][p] = ffma2(v.y, d11, ffma2(v.x, d10, z[1][p]));
        z[2][p] = ffma2(v.y, d21, ffma2(v.x, d20, z[2][p]));
        z[3][p] = ffma2(v.y, d31, ffma2(v.x, d30, z[3][p]));
    }
}

// full k-group (4 k) from a float4-per-gate weight vector
template <int KDIM, int NP>
__device__ __forceinline__ void kbody4(const float4 w[4],
                                       const float2* __restrict__ hp,
                                       ull z[4][NP], int kidx) {
    k2body<KDIM, NP>(make_float2(w[0].x, w[0].y), make_float2(w[1].x, w[1].y),
                     make_float2(w[2].x, w[2].y), make_float2(w[3].x, w[3].y),
                     hp, z, 2 * kidx);
    k2body<KDIM, NP>(make_float2(w[0].z, w[0].w), make_float2(w[1].z, w[1].w),
                     make_float2(w[2].z, w[2].w), make_float2(w[3].z, w[3].w),
                     hp, z, 2 * kidx + 1);
}

// Streamed panel: Wt already offset to (kbase row, gt=0, j). Row stride 512
// float4; gt stride 128. Distance-1 rolling prefetch (+2 pad rows exist) —
// only w0[4]+wn[4] = 32 weight regs live (distance-2's 48 spilled at NG=4).
template <int KDIM, int KG, int NP>
__device__ __forceinline__ void panel_g4(const float4* __restrict__ Wt,
                                         const float2* __restrict__ hp,
                                         int kbase, ull z[4][NP]) {
    float4 w0[4];
#pragma unroll
    for (int gt = 0; gt < 4; ++gt) w0[gt] = Wt[gt * 128];
#pragma unroll 1
    for (int kg = 0; kg < KG; ++kg) {
        float4 wn[4];
#pragma unroll
        for (int gt = 0; gt < 4; ++gt) wn[gt] = Wt[(size_t)(kg + 1) * 512 + gt * 128];
        kbody4<KDIM, NP>(w0, hp, z, kbase + kg);
#pragma unroll
        for (int gt = 0; gt < 4; ++gt) w0[gt] = wn[gt];
    }
}

// Cached panel: Ws already offset to j within the cache.
template <int KDIM, int KG, int NP>
__device__ __forceinline__ void panel_s4(const float4* __restrict__ Ws,
                                         const float2* __restrict__ hp,
                                         int kbase, ull z[4][NP]) {
#pragma unroll 1
    for (int kg = 0; kg < KG; ++kg) {
        float4 w[4];
#pragma unroll
        for (int gt = 0; gt < 4; ++gt) w[gt] = Ws[kg * 512 + gt * 128];
        kbody4<KDIM, NP>(w, hp, z, kbase + kg);
    }
}

template <int NP>
__device__ __forceinline__ void l0_gemm(const float4* __restrict__ sWih0,
                                        const float4* __restrict__ sWhh0,
                                        const float2* __restrict__ xi,
                                        const float2* __restrict__ h0,
                                        ull z[4][NP], int j, int ks) {
    if (ks == 0) {
        panel_s4<F_, 4, NP>(sWih0 + j, xi, 0, z);
        panel_s4<H_, CWHH, NP>(sWhh0 + j, h0, 0, z);
        panel_g4<H_, 16 - CWHH, NP>(g_Whh0p + CWHH * 512 + j, h0, CWHH, z);
    } else {
        panel_s4<F_, 4, NP>(sWih0 + 4 * 512 + j, xi, 4, z);
        panel_g4<H_, 16, NP>(g_Whh0p + 16 * 512 + j, h0, 16, z);
    }
}

template <int NP>
__device__ __forceinline__ void l1_gemm(const float2* __restrict__ h0,
                                        const float2* __restrict__ h1,
                                        ull z[4][NP], int j, int ks) {
    if (ks == 0) {
        panel_g4<H_, 16, NP>(g_Wih1p + j, h0, 0, z);
        panel_g4<H_, 16, NP>(g_Whh1p + j, h1, 0, z);
    } else {
        panel_g4<H_, 16, NP>(g_Wih1p + 16 * 512 + j, h0, 16, z);
        panel_g4<H_, 16, NP>(g_Whh1p + 16 * 512 + j, h1, 16, z);
    }
}

template <int NP>
__device__ __forceinline__ void store_z(ull z[4][NP], ull* __restrict__ zmy,
                                        int j, int pofs) {
#pragma unroll
    for (int gt = 0; gt < 4; ++gt)
#pragma unroll
        for (int p = 0; p < NP; ++p)
            zmy[(gt * 128 + j) * PST + pofs + p] = z[gt][p];
}

extern __shared__ float4 smem4[];

__global__ void __launch_bounds__(NT, 1)
lstm_persistent(const float* __restrict__ x,
                const float* __restrict__ b0,
                const float* __restrict__ b1,
                const float* __restrict__ Wfc,
                const float* __restrict__ bfc,
                float* __restrict__ out) {
    // SMEM: [Wih0 8 rows][Whh0 CWHH rows][sb0,sb1][h0,c0,h1,c1][zbuf x2][x x2]
    float4* sWih0 = smem4;                          // 8*512 f4 = 64KB
    float4* sWhh0 = smem4 + 8 * 512;                // CWHH*512 f4
    float* sb0 = (float*)(smem4 + (8 + CWHH) * 512);  // 512 f
    float* sb1 = sb0 + 512;                           // 512 f
    float2* hbase = (float2*)(sb1 + 512);
    float2* h0p = hbase;                 // P_*H_
    float2* c0p = h0p + P_ * H_;
    float2* h1p = c0p + P_ * H_;
    float2* c1p = h1p + P_ * H_;
    ull* zbu0 = (ull*)(c1p + P_ * H_);   // 512*PST per ksplit
    ull* zbu1 = zbu0 + 512 * PST;
    float2* xb[2] = { (float2*)(zbu1 + 512 * PST),
                      (float2*)(zbu1 + 512 * PST) + P_ * F_ };

    const int tid = threadIdx.x;
    const int j = tid & 127;             // output index
    const int ks = (tid >> 7) & 1;       // k-split
    const int half = tid >> 8;           // batch-pair half
    const int b_base = blockIdx.x * BT;
    const int nb = min(BT, B_ - b_base);
    ull* zmy = ks ? zbu1 : zbu0;

    // fill weight caches + biases (once per launch)
    for (int i = tid; i < 8 * 512; i += NT) sWih0[i] = g_Wih0p[i];
    for (int i = tid; i < CWHH * 512; i += NT) sWhh0[i] = g_Whh0p[i];
    if (tid < 512) { sb0[tid] = b0[tid]; sb1[tid] = b1[tid]; }
    // zero h/c
    for (int i = tid; i < 4 * P_ * H_; i += NT) hbase[i] = make_float2(0.f, 0.f);
    // stage x(t=0)
    for (int i = tid; i < BT * F_; i += NT) {
        int b = i / F_, f = i % F_;
        float v = (b < nb) ? x[((size_t)(b_base + b) * T_) * F_ + f] : 0.0f;
        ((float*)xb[0])[(b >> 1) * F_ * 2 + f * 2 + (b & 1)] = v;
    }
    __syncthreads();

    int cur = 0;
    for (int t = 0; t < T_; ++t) {
        // ---------- layer 0 GEMM ----------
        if (half == 0) {
            ull z[4][4];
#pragma unroll
            for (int gt = 0; gt < 4; ++gt)
#pragma unroll
                for (int p = 0; p < 4; ++p) z[gt][p] = 0ull;
            l0_gemm<4>(sWih0, sWhh0, xb[cur], h0p, z, j, ks);
            store_z<4>(z, zmy, j, 0);
        } else {
            ull z[4][3];
#pragma unroll
            for (int gt = 0; gt < 4; ++gt)
#pragma unroll
                for (int p = 0; p < 3; ++p) z[gt][p] = 0ull;
            l0_gemm<3>(sWih0, sWhh0, xb[cur] + 4 * F_, h0p + 4 * H_, z, j, ks);
            store_z<3>(z, zmy, j, 4);
        }
        __syncthreads();

        // ---------- layer 0 gate update ----------
        for (int i = tid; i < P_ * H_; i += NT) {
            int p = i >> 7, j2 = i & 127;
            float2 vA, vB;
            vA = u2f(zbu0[(j2      ) * PST + p]); vB = u2f(zbu1[(j2      ) * PST + p]);
            float zix = vA.x + vB.x + sb0[j2],        ziy = vA.y + vB.y + sb0[j2];
            vA = u2f(zbu0[(j2 + 128) * PST + p]); vB = u2f(zbu1[(j2 + 128) * PST + p]);
            float zfx = vA.x + vB.x + sb0[j2 + 128],  zfy = vA.y + vB.y + sb0[j2 + 128];
            vA = u2f(zbu0[(j2 + 256) * PST + p]); vB = u2f(zbu1[(j2 + 256) * PST + p]);
            float zgx = vA.x + vB.x + sb0[j2 + 256],  zgy = vA.y + vB.y + sb0[j2 + 256];
            vA = u2f(zbu0[(j2 + 384) * PST + p]); vB = u2f(zbu1[(j2 + 384) * PST + p]);
            float zox = vA.x + vB.x + sb0[j2 + 384],  zoy = vA.y + vB.y + sb0[j2 + 384];
            float2 c = c0p[p * H_ + j2];
            float2 nc, nh;
            nc.x = sigm(zfx) * c.x + sigm(zix) * tanh_f(zgx);
            nc.y = sigm(zfy) * c.y + sigm(ziy) * tanh_f(zgy);
            nh.x = sigm(zox) * tanh_f(nc.x);
            nh.y = sigm(zoy) * tanh_f(nc.y);
            c0p[p * H_ + j2] = nc;
            h0p[p * H_ + j2] = nh;
        }
        __syncthreads();

        // ---------- layer 1 GEMM ----------
        if (half == 0) {
            ull z[4][4];
#pragma unroll
            for (int gt = 0; gt < 4; ++gt)
#pragma unroll
                for (int p = 0; p < 4; ++p) z[gt][p] = 0ull;
            l1_gemm<4>(h0p, h1p, z, j, ks);
            store_z<4>(z, zmy, j, 0);
        } else {
            ull z[4][3];
#pragma unroll
            for (int gt = 0; gt < 4; ++gt)
#pragma unroll
                for (int p = 0; p < 3; ++p) z[gt][p] = 0ull;
            l1_gemm<3>(h0p + 4 * H_, h1p + 4 * H_, z, j, ks);
            store_z<3>(z, zmy, j, 4);
        }
        // stage x(t+1) into the other buffer
        if (t + 1 < T_) {
            for (int i = tid; i < BT * F_; i += NT) {
                int b = i / F_, f = i % F_;
                float v = (b < nb)
                    ? x[((size_t)(b_base + b) * T_ + (t + 1)) * F_ + f]
                    : 0.0f;
                ((float*)xb[cur ^ 1])[(b >> 1) * F_ * 2 + f * 2 + (b & 1)] = v;
            }
        }
        __syncthreads();

        // ---------- layer 1 gate update ----------
        for (int i = tid; i < P_ * H_; i += NT) {
            int p = i >> 7, j2 = i & 127;
            float2 vA, vB;
            vA = u2f(zbu0[(j2      ) * PST + p]); vB = u2f(zbu1[(j2      ) * PST + p]);
            float zix = vA.x + vB.x + sb1[j2],        ziy = vA.y + vB.y + sb1[j2];
            vA = u2f(zbu0[(j2 + 128) * PST + p]); vB = u2f(zbu1[(j2 + 128) * PST + p]);
            float zfx = vA.x + vB.x + sb1[j2 + 128],  zfy = vA.y + vB.y + sb1[j2 + 128];
            vA = u2f(zbu0[(j2 + 256) * PST + p]); vB = u2f(zbu1[(j2 + 256) * PST + p]);
            float zgx = vA.x + vB.x + sb1[j2 + 256],  zgy = vA.y + vB.y + sb1[j2 + 256];
            vA = u2f(zbu0[(j2 + 384) * PST + p]); vB = u2f(zbu1[(j2 + 384) * PST + p]);
            float zox = vA.x + vB.x + sb1[j2 + 384],  zoy = vA.y + vB.y + sb1[j2 + 384];
            float2 c = c1p[p * H_ + j2];
            float2 nc, nh;
            nc.x = sigm(zfx) * c.x + sigm(zix) * tanh_f(zgx);
            nc.y = sigm(zfy) * c.y + sigm(ziy) * tanh_f(zgy);
            nh.x = sigm(zox) * tanh_f(nc.x);
            nh.y = sigm(zoy) * tanh_f(nc.y);
            c1p[p * H_ + j2] = nc;
            h1p[p * H_ + j2] = nh;
        }
        __syncthreads();
        cur ^= 1;
    }

    // FC head
    if (tid < nb) {
        float s = bfc[0];
#pragma unroll
        for (int k = 0; k < H_; ++k) {
            float2 hv = h1p[(tid >> 1) * H_ + k];
            float h = (tid & 1) ? hv.y : hv.x;
            s = fmaf(h, Wfc[k], s);
        }
        out[b_base + tid] = s;
    }
}

extern "C" void kernel_launch(void* const* d_in, const int* in_sizes, int n_in,
                              void* d_out, int out_size) {
    const float* x    = (const float*)d_in[0];
    const float* Wih0 = (const float*)d_in[1];
    const float* Whh0 = (const float*)d_in[2];
    const float* b0   = (const float*)d_in[3];
    const float* Wih1 = (const float*)d_in[4];
    const float* Whh1 = (const float*)d_in[5];
    const float* b1   = (const float*)d_in[6];
    const float* Wfc  = (const float*)d_in[7];
    const float* bfc  = (const float*)d_in[8];
    float* out = (float*)d_out;
    (void)in_sizes; (void)n_in; (void)out_size;

    prep<<<64, 256>>>(Wih0, Whh0, Wih1, Whh1);

    const int smem_bytes =
        (8 + CWHH) * 512 * (int)sizeof(float4) +   // weight caches
        2 * 512 * (int)sizeof(float) +             // biases
        4 * P_ * H_ * (int)sizeof(float2) +        // h/c
        2 * 512 * PST * (int)sizeof(ull) +         // split-K zbufs
        2 * P_ * F_ * (int)sizeof(float2);         // x double buffer
    cudaFuncSetAttribute(lstm_persistent,
                         cudaFuncAttributeMaxDynamicSharedMemorySize,
                         smem_bytes);

    lstm_persistent<<<(B_ + BT - 1) / BT, NT, smem_bytes>>>(
        x, b0, b1, Wfc, bfc, out);
}

// round 14
// speedup vs baseline: 1.3687x; 1.0497x over previous
#include <cuda_runtime.h>
#include <math.h>

// Problem constants
#define B_  2048
#define T_  512
#define F_  32
#define H_  128
#define BT  14       // batch rows per CTA -> 147 CTAs = one wave on 148 SMs
#define P_  7        // batch pairs per CTA
#define NT  512      // (half: pairs 0-3 / 4-6) x (ksplit: lo/hi K) x 128 j
#define PST 7        // zbuf stride in ull per gate row

typedef unsigned long long ull;

// Weights laid out [kg][gt][j] float4 (4 consecutive k per load):
// index = (kg*4 + gt)*128 + j ; gate = gt*128 + j ; k = 4*kg.
// Lanes (consecutive j) are fully coalesced. +2 kg rows pad for prefetch.
__device__ float4 g_Wih0p[(8 + 2) * 512];
__device__ float4 g_Whh0p[(32 + 2) * 512];
__device__ float4 g_Wih1p[(32 + 2) * 512];
__device__ float4 g_Whh1p[(32 + 2) * 512];

__global__ void prep(const float* __restrict__ Wih0,
                     const float* __restrict__ Whh0,
                     const float* __restrict__ Wih1,
                     const float* __restrict__ Whh1) {
    int idx = blockIdx.x * blockDim.x + threadIdx.x;  // 0..16383
    int j = idx & 127, gt = (idx >> 7) & 3, kg = idx >> 9;
    int gate = gt * 128 + j;
    g_Whh0p[idx] = *(const float4*)(Whh0 + gate * 128 + 4 * kg);
    g_Wih1p[idx] = *(const float4*)(Wih1 + gate * 128 + 4 * kg);
    g_Whh1p[idx] = *(const float4*)(Whh1 + gate * 128 + 4 * kg);
    if (kg < 8)
        g_Wih0p[idx] = *(const float4*)(Wih0 + gate * 32 + 4 * kg);
}

__device__ __forceinline__ ull ffma2(ull a, ull b, ull c) {
    ull d;
    asm("fma.rn.f32x2 %0, %1, %2, %3;" : "=l"(d) : "l"(a), "l"(b), "l"(c));
    return d;
}
__device__ __forceinline__ ull dup2(float w) {
    ull d;
    asm("mov.b64 %0, {%1, %1};" : "=l"(d) : "f"(w));
    return d;
}
__device__ __forceinline__ float2 u2f(ull v) {
    float2 r;
    asm("mov.b64 {%0, %1}, %2;" : "=f"(r.x), "=f"(r.y) : "l"(v));
    return r;
}
__device__ __forceinline__ float sigm(float x) {
    return 1.0f / (1.0f + __expf(-x));
}
__device__ __forceinline__ float tanh_f(float x) {
    float e = __expf(-2.0f * fabsf(x));
    float t = (1.0f - e) / (1.0f + e);
    return x >= 0.0f ? t : -t;
}

// 2 k-values, 4 gates, NP pairs. kp = 16B index into each pair's h row.
template <int KDIM, int NP>
__device__ __forceinline__ void k2body(float2 w0, float2 w1, float2 w2, float2 w3,
                                       const float2* __restrict__ hp,
                                       ull z[4][NP], int kp) {
    ull d00 = dup2(w0.x), d01 = dup2(w0.y);
    ull d10 = dup2(w1.x), d11 = dup2(w1.y);
    ull d20 = dup2(w2.x), d21 = dup2(w2.y);
    ull d30 = dup2(w3.x), d31 = dup2(w3.y);
#pragma unroll
    for (int p = 0; p < NP; ++p) {
        ulonglong2 v = ((const ulonglong2*)(hp + p * KDIM))[kp];
        z[0][p] = ffma2(v.y, d01, ffma2(v.x, d00, z[0][p]));
        z[1][p] = ffma2(v.y, d11, ffma2(v.x, d10, z[1][p]));
        z[2][p] = ffma2(v.y, d21, ffma2(v.x, d20, z[2][p]));
        z[3][p] = ffma2(v.y, d31, ffma2(v.x, d30, z[3][p]));
    }
}

// full k-group (4 k) from a float4-per-gate weight vector
template <int KDIM, int NP>
__device__ __forceinline__ void kbody4(const float4 w[4],
                                       const float2* __restrict__ hp,
                                       ull z[4][NP], int kidx) {
    k2body<KDIM, NP>(make_float2(w[0].x, w[0].y), make_float2(w[1].x, w[1].y),
                     make_float2(w[2].x, w[2].y), make_float2(w[3].x, w[3].y),
                     hp, z, 2 * kidx);
    k2body<KDIM, NP>(make_float2(w[0].z, w[0].w), make_float2(w[1].z, w[1].w),
                     make_float2(w[2].z, w[2].w), make_float2(w[3].z, w[3].w),
                     hp, z, 2 * kidx + 1);
}

// Streamed panel: Wt already offset to (kbase row, gt=0, j). Row stride 512
// float4; gt stride 128. Distance-1 rolling prefetch (+2 pad rows exist).
template <int KDIM, int KG, int NP>
__device__ __forceinline__ void panel_g4(const float4* __restrict__ Wt,
                                         const float2* __restrict__ hp,
                                         int kbase, ull z[4][NP]) {
    float4 w0[4];
#pragma unroll
    for (int gt = 0; gt < 4; ++gt) w0[gt] = Wt[gt * 128];
#pragma unroll 1
    for (int kg = 0; kg < KG; ++kg) {
        float4 wn[4];
#pragma unroll
        for (int gt = 0; gt < 4; ++gt) wn[gt] = Wt[(size_t)(kg + 1) * 512 + gt * 128];
        kbody4<KDIM, NP>(w0, hp, z, kbase + kg);
#pragma unroll
        for (int gt = 0; gt < 4; ++gt) w0[gt] = wn[gt];
    }
}

// Cached panel: Ws already offset to j within the cache.
template <int KDIM, int KG, int NP>
__device__ __forceinline__ void panel_s4(const float4* __restrict__ Ws,
                                         const float2* __restrict__ hp,
                                         int kbase, ull z[4][NP]) {
#pragma unroll 1
    for (int kg = 0; kg < KG; ++kg) {
        float4 w[4];
#pragma unroll
        for (int gt = 0; gt < 4; ++gt) w[gt] = Ws[kg * 512 + gt * 128];
        kbody4<KDIM, NP>(w, hp, z, kbase + kg);
    }
}

template <int NP>
__device__ __forceinline__ void l0_gemm(const float4* __restrict__ sWih0,
                                        const float2* __restrict__ xi,
                                        const float2* __restrict__ h0,
                                        ull z[4][NP], int j, int ks) {
    if (ks == 0) {
        panel_s4<F_, 4, NP>(sWih0 + j, xi, 0, z);
        panel_g4<H_, 16, NP>(g_Whh0p + j, h0, 0, z);
    } else {
        panel_s4<F_, 4, NP>(sWih0 + 4 * 512 + j, xi, 4, z);
        panel_g4<H_, 16, NP>(g_Whh0p + 16 * 512 + j, h0, 16, z);
    }
}

template <int NP>
__device__ __forceinline__ void l1_gemm(const float2* __restrict__ h0,
                                        const float2* __restrict__ h1,
                                        ull z[4][NP], int j, int ks) {
    if (ks == 0) {
        panel_g4<H_, 16, NP>(g_Wih1p + j, h0, 0, z);
        panel_g4<H_, 16, NP>(g_Whh1p + j, h1, 0, z);
    } else {
        panel_g4<H_, 16, NP>(g_Wih1p + 16 * 512 + j, h0, 16, z);
        panel_g4<H_, 16, NP>(g_Whh1p + 16 * 512 + j, h1, 16, z);
    }
}

template <int NP>
__device__ __forceinline__ void store_z(ull z[4][NP], ull* __restrict__ zmy,
                                        int j, int pofs) {
#pragma unroll
    for (int gt = 0; gt < 4; ++gt)
#pragma unroll
        for (int p = 0; p < NP; ++p)
            zmy[(gt * 128 + j) * PST + pofs + p] = z[gt][p];
}

// Gate update for one layer: sums the two ksplit partials + bias, applies
// LSTM nonlinearity, updates c (SMEM) and h (SMEM).
__device__ __forceinline__ void gate_update_layer(const ull* __restrict__ zb0,
                                                  const ull* __restrict__ zb1,
                                                  const float* __restrict__ sb,
                                                  float2* __restrict__ cp,
                                                  float2* __restrict__ hp,
                                                  int tid) {
    for (int i = tid; i < P_ * H_; i += NT) {
        int p = i >> 7, j2 = i & 127;
        float2 vA, vB;
        vA = u2f(zb0[(j2      ) * PST + p]); vB = u2f(zb1[(j2      ) * PST + p]);
        float zix = vA.x + vB.x + sb[j2],        ziy = vA.y + vB.y + sb[j2];
        vA = u2f(zb0[(j2 + 128) * PST + p]); vB = u2f(zb1[(j2 + 128) * PST + p]);
        float zfx = vA.x + vB.x + sb[j2 + 128],  zfy = vA.y + vB.y + sb[j2 + 128];
        vA = u2f(zb0[(j2 + 256) * PST + p]); vB = u2f(zb1[(j2 + 256) * PST + p]);
        float zgx = vA.x + vB.x + sb[j2 + 256],  zgy = vA.y + vB.y + sb[j2 + 256];
        vA = u2f(zb0[(j2 + 384) * PST + p]); vB = u2f(zb1[(j2 + 384) * PST + p]);
        float zox = vA.x + vB.x + sb[j2 + 384],  zoy = vA.y + vB.y + sb[j2 + 384];
        float2 c = cp[p * H_ + j2];
        float2 nc, nh;
        nc.x = sigm(zfx) * c.x + sigm(zix) * tanh_f(zgx);
        nc.y = sigm(zfy) * c.y + sigm(ziy) * tanh_f(zgy);
        nh.x = sigm(zox) * tanh_f(nc.x);
        nh.y = sigm(zoy) * tanh_f(nc.y);
        cp[p * H_ + j2] = nc;
        hp[p * H_ + j2] = nh;
    }
}

extern __shared__ float4 smem4[];

__global__ void __launch_bounds__(NT, 1)
lstm_persistent(const float* __restrict__ x,
                const float* __restrict__ b0,
                const float* __restrict__ b1,
                const float* __restrict__ Wfc,
                const float* __restrict__ bfc,
                float* __restrict__ out) {
    // SMEM: [Wih0 8 rows][sb0,sb1][h0,c0,h1,c1][z0buf x2][z1buf x2][x x2]
    float4* sWih0 = smem4;                            // 8*512 f4 = 64KB
    float* sb0 = (float*)(smem4 + 8 * 512);           // 512 f
    float* sb1 = sb0 + 512;                           // 512 f
    float2* hbase = (float2*)(sb1 + 512);
    float2* h0p = hbase;                 // P_*H_
    float2* c0p = h0p + P_ * H_;
    float2* h1p = c0p + P_ * H_;
    float2* c1p = h1p + P_ * H_;
    ull* z0bu0 = (ull*)(c1p + P_ * H_);  // 512*PST each
    ull* z0bu1 = z0bu0 + 512 * PST;
    ull* z1bu0 = z0bu1 + 512 * PST;
    ull* z1bu1 = z1bu0 + 512 * PST;
    float2* xb[2] = { (float2*)(z1bu1 + 512 * PST),
                      (float2*)(z1bu1 + 512 * PST) + P_ * F_ };

    const int tid = threadIdx.x;
    const int j = tid & 127;             // output index
    const int ks = (tid >> 7) & 1;       // k-split
    const int half = tid >> 8;           // batch-pair half
    const int b_base = blockIdx.x * BT;
    const int nb = min(BT, B_ - b_base);
    ull* z0my = ks ? z0bu1 : z0bu0;
    ull* z1my = ks ? z1bu1 : z1bu0;

    // fill weight cache + biases (once per launch)
    for (int i = tid; i < 8 * 512; i += NT) sWih0[i] = g_Wih0p[i];
    if (tid < 512) { sb0[tid] = b0[tid]; sb1[tid] = b1[tid]; }
    // zero h/c
    for (int i = tid; i < 4 * P_ * H_; i += NT) hbase[i] = make_float2(0.f, 0.f);
    // stage x(t=0)
    for (int i = tid; i < BT * F_; i += NT) {
        int b = i / F_, f = i % F_;
        float v = (b < nb) ? x[((size_t)(b_base + b) * T_) * F_ + f] : 0.0f;
        ((float*)xb[0])[(b >> 1) * F_ * 2 + f * 2 + (b & 1)] = v;
    }
    __syncthreads();

    // Software-pipelined: iteration t runs l0-GEMM(t) and l1-GEMM(t-1) in ONE
    // phase (inputs h0[t-1], h1[t-2], x[t] all ready), then updates both.
    int cur = 0;
    for (int t = 0; t < T_; ++t) {
        // ---------- G phase: both layers' GEMMs ----------
        if (half == 0) {
            ull z[4][4];
#pragma unroll
            for (int gt = 0; gt < 4; ++gt)
#pragma unroll
                for (int p = 0; p < 4; ++p) z[gt][p] = 0ull;
            l0_gemm<4>(sWih0, xb[cur], h0p, z, j, ks);
            store_z<4>(z, z0my, j, 0);
            if (t > 0) {
#pragma unroll
                for (int gt = 0; gt < 4; ++gt)
#pragma unroll
                    for (int p = 0; p < 4; ++p) z[gt][p] = 0ull;
                l1_gemm<4>(h0p, h1p, z, j, ks);
                store_z<4>(z, z1my, j, 0);
            }
        } else {
            ull z[4][3];
#pragma unroll
            for (int gt = 0; gt < 4; ++gt)
#pragma unroll
                for (int p = 0; p < 3; ++p) z[gt][p] = 0ull;
            l0_gemm<3>(sWih0, xb[cur] + 4 * F_, h0p + 4 * H_, z, j, ks);
            store_z<3>(z, z0my, j, 4);
            if (t > 0) {
#pragma unroll
                for (int gt = 0; gt < 4; ++gt)
#pragma unroll
                    for (int p = 0; p < 3; ++p) z[gt][p] = 0ull;
                l1_gemm<3>(h0p + 4 * H_, h1p + 4 * H_, z, j, ks);
                store_z<3>(z, z1my, j, 4);
            }
        }
        __syncthreads();

        // ---------- U phase: both gate updates + x staging ----------
        gate_update_layer(z0bu0, z0bu1, sb0, c0p, h0p, tid);   // h0[t]
        if (t > 0)
            gate_update_layer(z1bu0, z1bu1, sb1, c1p, h1p, tid); // h1[t-1]
        if (t + 1 < T_) {
            for (int i = tid; i < BT * F_; i += NT) {
                int b = i / F_, f = i % F_;
                float v = (b < nb)
                    ? x[((size_t)(b_base + b) * T_ + (t + 1)) * F_ + f]
                    : 0.0f;
                ((float*)xb[cur ^ 1])[(b >> 1) * F_ * 2 + f * 2 + (b & 1)] = v;
            }
        }
        __syncthreads();
        cur ^= 1;
    }

    // ---------- epilogue: l1 step T-1 ----------
    if (half == 0) {
        ull z[4][4];
#pragma unroll
        for (int gt = 0; gt < 4; ++gt)
#pragma unroll
            for (int p = 0; p < 4; ++p) z[gt][p] = 0ull;
        l1_gemm<4>(h0p, h1p, z, j, ks);
        store_z<4>(z, z1my, j, 0);
    } else {
        ull z[4][3];
#pragma unroll
        for (int gt = 0; gt < 4; ++gt)
#pragma unroll
            for (int p = 0; p < 3; ++p) z[gt][p] = 0ull;
        l1_gemm<3>(h0p + 4 * H_, h1p + 4 * H_, z, j, ks);
        store_z<3>(z, z1my, j, 4);
    }
    __syncthreads();
    gate_update_layer(z1bu0, z1bu1, sb1, c1p, h1p, tid);       // h1[T-1]
    __syncthreads();

    // FC head
    if (tid < nb) {
        float s = bfc[0];
#pragma unroll
        for (int k = 0; k < H_; ++k) {
            float2 hv = h1p[(tid >> 1) * H_ + k];
            float h = (tid & 1) ? hv.y : hv.x;
            s = fmaf(h, Wfc[k], s);
        }
        out[b_base + tid] = s;
    }
}

extern "C" void kernel_launch(void* const* d_in, const int* in_sizes, int n_in,
                              void* d_out, int out_size) {
    const float* x    = (const float*)d_in[0];
    const float* Wih0 = (const float*)d_in[1];
    const float* Whh0 = (const float*)d_in[2];
    const float* b0   = (const float*)d_in[3];
    const float* Wih1 = (const float*)d_in[4];
    const float* Whh1 = (const float*)d_in[5];
    const float* b1   = (const float*)d_in[6];
    const float* Wfc  = (const float*)d_in[7];
    const float* bfc  = (const float*)d_in[8];
    float* out = (float*)d_out;
    (void)in_sizes; (void)n_in; (void)out_size;

    prep<<<64, 256>>>(Wih0, Whh0, Wih1, Whh1);

    const int smem_bytes =
        8 * 512 * (int)sizeof(float4) +            // Wih0 cache
        2 * 512 * (int)sizeof(float) +             // biases
        4 * P_ * H_ * (int)sizeof(float2) +        // h/c
        4 * 512 * PST * (int)sizeof(ull) +         // zbufs (2 layers x 2 ks)
        2 * P_ * F_ * (int)sizeof(float2);         // x double buffer
    cudaFuncSetAttribute(lstm_persistent,
                         cudaFuncAttributeMaxDynamicSharedMemorySize,
                         smem_bytes);

    lstm_persistent<<<(B_ + BT - 1) / BT, NT, smem_bytes>>>(
        x, b0, b1, Wfc, bfc, out);
}

// round 15
// speedup vs baseline: 1.3897x; 1.0153x over previous
#include <cuda_runtime.h>
#include <math.h>

// Problem constants
#define B_  2048
#define T_  512
#define F_  32
#define H_  128
#define BT  14       // batch rows per CTA -> 147 CTAs = one wave on 148 SMs
#define P_  7        // batch pairs per CTA
#define NT  512      // (half) x (ksplit: lo/hi K) x 128 j
#define PST 7        // zbuf stride in ull per gate row

typedef unsigned long long ull;

// Weights laid out [kg][gt][j] float4 (4 consecutive k per load):
// index = (kg*4 + gt)*128 + j ; gate = gt*128 + j ; k = 4*kg.
// Lanes (consecutive j) are fully coalesced. +2 kg rows pad for prefetch.
__device__ float4 g_Wih0p[(8 + 2) * 512];
__device__ float4 g_Whh0p[(32 + 2) * 512];
__device__ float4 g_Wih1p[(32 + 2) * 512];
__device__ float4 g_Whh1p[(32 + 2) * 512];

__global__ void prep(const float* __restrict__ Wih0,
                     const float* __restrict__ Whh0,
                     const float* __restrict__ Wih1,
                     const float* __restrict__ Whh1) {
    int idx = blockIdx.x * blockDim.x + threadIdx.x;  // 0..16383
    int j = idx & 127, gt = (idx >> 7) & 3, kg = idx >> 9;
    int gate = gt * 128 + j;
    g_Whh0p[idx] = *(const float4*)(Whh0 + gate * 128 + 4 * kg);
    g_Wih1p[idx] = *(const float4*)(Wih1 + gate * 128 + 4 * kg);
    g_Whh1p[idx] = *(const float4*)(Whh1 + gate * 128 + 4 * kg);
    if (kg < 8)
        g_Wih0p[idx] = *(const float4*)(Wih0 + gate * 32 + 4 * kg);
}

__device__ __forceinline__ ull ffma2(ull a, ull b, ull c) {
    ull d;
    asm("fma.rn.f32x2 %0, %1, %2, %3;" : "=l"(d) : "l"(a), "l"(b), "l"(c));
    return d;
}
__device__ __forceinline__ ull addx2(ull a, ull b) {
    ull r;
    asm("add.rn.f32x2 %0, %1, %2;" : "=l"(r) : "l"(a), "l"(b));
    return r;
}
__device__ __forceinline__ ull dup2(float w) {
    ull d;
    asm("mov.b64 %0, {%1, %1};" : "=l"(d) : "f"(w));
    return d;
}
__device__ __forceinline__ float2 u2f(ull v) {
    float2 r;
    asm("mov.b64 {%0, %1}, %2;" : "=f"(r.x), "=f"(r.y) : "l"(v));
    return r;
}
__device__ __forceinline__ float sigm(float x) {
    return 1.0f / (1.0f + __expf(-x));
}
__device__ __forceinline__ float tanh_f(float x) {
    float e = __expf(-2.0f * fabsf(x));
    float t = (1.0f - e) / (1.0f + e);
    return x >= 0.0f ? t : -t;
}

// 2 k-values, 4 gates, NP pairs. kp = 16B index into each pair's h row.
template <int KDIM, int NP>
__device__ __forceinline__ void k2body(float2 w0, float2 w1, float2 w2, float2 w3,
                                       const float2* __restrict__ hp,
                                       ull z[4][NP], int kp) {
    ull d00 = dup2(w0.x), d01 = dup2(w0.y);
    ull d10 = dup2(w1.x), d11 = dup2(w1.y);
    ull d20 = dup2(w2.x), d21 = dup2(w2.y);
    ull d30 = dup2(w3.x), d31 = dup2(w3.y);
#pragma unroll
    for (int p = 0; p < NP; ++p) {
        ulonglong2 v = ((const ulonglong2*)(hp + p * KDIM))[kp];
        z[0][p] = ffma2(v.y, d01, ffma2(v.x, d00, z[0][p]));
        z[1][p] = ffma2(v.y, d11, ffma2(v.x, d10, z[1][p]));
        z[2][p] = ffma2(v.y, d21, ffma2(v.x, d20, z[2][p]));
        z[3][p] = ffma2(v.y, d31, ffma2(v.x, d30, z[3][p]));
    }
}

// full k-group (4 k) from a float4-per-gate weight vector
template <int KDIM, int NP>
__device__ __forceinline__ void kbody4(const float4 w[4],
                                       const float2* __restrict__ hp,
                                       ull z[4][NP], int kidx) {
    k2body<KDIM, NP>(make_float2(w[0].x, w[0].y), make_float2(w[1].x, w[1].y),
                     make_float2(w[2].x, w[2].y), make_float2(w[3].x, w[3].y),
                     hp, z, 2 * kidx);
    k2body<KDIM, NP>(make_float2(w[0].z, w[0].w), make_float2(w[1].z, w[1].w),
                     make_float2(w[2].z, w[2].w), make_float2(w[3].z, w[3].w),
                     hp, z, 2 * kidx + 1);
}

// Streamed panel: Wt already offset to (kbase row, gt=0, j). Row stride 512
// float4; gt stride 128. Distance-1 rolling prefetch (+2 pad rows exist).
template <int KDIM, int KG, int NP>
__device__ __forceinline__ void panel_g4(const float4* __restrict__ Wt,
                                         const float2* __restrict__ hp,
                                         int kbase, ull z[4][NP]) {
    float4 w0[4];
#pragma unroll
    for (int gt = 0; gt < 4; ++gt) w0[gt] = Wt[gt * 128];
#pragma unroll 1
    for (int kg = 0; kg < KG; ++kg) {
        float4 wn[4];
#pragma unroll
        for (int gt = 0; gt < 4; ++gt) wn[gt] = Wt[(size_t)(kg + 1) * 512 + gt * 128];
        kbody4<KDIM, NP>(w0, hp, z, kbase + kg);
#pragma unroll
        for (int gt = 0; gt < 4; ++gt) w0[gt] = wn[gt];
    }
}

// Cached panel: Ws already offset to j within the cache.
template <int KDIM, int KG, int NP>
__device__ __forceinline__ void panel_s4(const float4* __restrict__ Ws,
                                         const float2* __restrict__ hp,
                                         int kbase, ull z[4][NP]) {
#pragma unroll 1
    for (int kg = 0; kg < KG; ++kg) {
        float4 w[4];
#pragma unroll
        for (int gt = 0; gt < 4; ++gt) w[gt] = Ws[kg * 512 + gt * 128];
        kbody4<KDIM, NP>(w, hp, z, kbase + kg);
    }
}

template <int NP>
__device__ __forceinline__ void l0_gemm(const float4* __restrict__ sWih0,
                                        const float2* __restrict__ xi,
                                        const float2* __restrict__ h0,
                                        ull z[4][NP], int j, int ks) {
    if (ks == 0) {
        panel_s4<F_, 4, NP>(sWih0 + j, xi, 0, z);
        panel_g4<H_, 16, NP>(g_Whh0p + j, h0, 0, z);
    } else {
        panel_s4<F_, 4, NP>(sWih0 + 4 * 512 + j, xi, 4, z);
        panel_g4<H_, 16, NP>(g_Whh0p + 16 * 512 + j, h0, 16, z);
    }
}

template <int NP>
__device__ __forceinline__ void l1_gemm(const float2* __restrict__ h0,
                                        const float2* __restrict__ h1,
                                        ull z[4][NP], int j, int ks) {
    if (ks == 0) {
        panel_g4<H_, 16, NP>(g_Wih1p + j, h0, 0, z);
        panel_g4<H_, 16, NP>(g_Whh1p + j, h1, 0, z);
    } else {
        panel_g4<H_, 16, NP>(g_Wih1p + 16 * 512 + j, h0, 16, z);
        panel_g4<H_, 16, NP>(g_Whh1p + 16 * 512 + j, h1, 16, z);
    }
}

template <int NP>
__device__ __forceinline__ void store_z(ull z[4][NP], ull* __restrict__ zmy,
                                        int j, int pofs) {
#pragma unroll
    for (int gt = 0; gt < 4; ++gt)
#pragma unroll
        for (int p = 0; p < NP; ++p)
            zmy[(gt * 128 + j) * PST + pofs + p] = z[gt][p];
}

// Gate update for one layer: packed-sums the two ksplit partials + dup'd bias,
// applies LSTM nonlinearity, updates c (SMEM) and h (SMEM).
__device__ __forceinline__ void gate_update_layer(const ull* __restrict__ zb0,
                                                  const ull* __restrict__ zb1,
                                                  const ull* __restrict__ sbd,
                                                  float2* __restrict__ cp,
                                                  float2* __restrict__ hp,
                                                  int tid) {
    for (int i = tid; i < P_ * H_; i += NT) {
        int p = i >> 7, j2 = i & 127;
        float2 vi = u2f(addx2(addx2(zb0[(j2      ) * PST + p],
                                    zb1[(j2      ) * PST + p]), sbd[j2]));
        float2 vf = u2f(addx2(addx2(zb0[(j2 + 128) * PST + p],
                                    zb1[(j2 + 128) * PST + p]), sbd[j2 + 128]));
        float2 vg = u2f(addx2(addx2(zb0[(j2 + 256) * PST + p],
                                    zb1[(j2 + 256) * PST + p]), sbd[j2 + 256]));
        float2 vo = u2f(addx2(addx2(zb0[(j2 + 384) * PST + p],
                                    zb1[(j2 + 384) * PST + p]), sbd[j2 + 384]));
        float2 c = cp[p * H_ + j2];
        float2 nc, nh;
        nc.x = sigm(vf.x) * c.x + sigm(vi.x) * tanh_f(vg.x);
        nc.y = sigm(vf.y) * c.y + sigm(vi.y) * tanh_f(vg.y);
        nh.x = sigm(vo.x) * tanh_f(nc.x);
        nh.y = sigm(vo.y) * tanh_f(nc.y);
        cp[p * H_ + j2] = nc;
        hp[p * H_ + j2] = nh;
    }
}

extern __shared__ float4 smem4[];

__global__ void __launch_bounds__(NT, 1)
lstm_persistent(const float* __restrict__ x,
                const float* __restrict__ b0,
                const float* __restrict__ b1,
                const float* __restrict__ Wfc,
                const float* __restrict__ bfc,
                float* __restrict__ out) {
    // SMEM: [Wih0 8 rows][sbd0,sbd1 dup'd biases][h0,c0,h1,c1][z0 x2][z1 x2][x x2]
    float4* sWih0 = smem4;                            // 8*512 f4 = 64KB
    ull* sbd0 = (ull*)(smem4 + 8 * 512);              // 512 ull
    ull* sbd1 = sbd0 + 512;                           // 512 ull
    float2* hbase = (float2*)(sbd1 + 512);
    float2* h0p = hbase;                 // P_*H_
    float2* c0p = h0p + P_ * H_;
    float2* h1p = c0p + P_ * H_;
    float2* c1p = h1p + P_ * H_;
    ull* z0bu0 = (ull*)(c1p + P_ * H_);  // 512*PST each
    ull* z0bu1 = z0bu0 + 512 * PST;
    ull* z1bu0 = z0bu1 + 512 * PST;
    ull* z1bu1 = z1bu0 + 512 * PST;
    float2* xb[2] = { (float2*)(z1bu1 + 512 * PST),
                      (float2*)(z1bu1 + 512 * PST) + P_ * F_ };

    const int tid = threadIdx.x;
    const int j = tid & 127;             // output index
    const int ks = (tid >> 7) & 1;       // k-split
    const int half = tid >> 8;           // batch-pair half (swapped per layer)
    const int b_base = blockIdx.x * BT;
    const int nb = min(BT, B_ - b_base);
    ull* z0my = ks ? z0bu1 : z0bu0;
    ull* z1my = ks ? z1bu1 : z1bu0;

    // fill weight cache + dup'd biases (once per launch)
    for (int i = tid; i < 8 * 512; i += NT) sWih0[i] = g_Wih0p[i];
    if (tid < 512) { sbd0[tid] = dup2(b0[tid]); sbd1[tid] = dup2(b1[tid]); }
    // zero h/c
    for (int i = tid; i < 4 * P_ * H_; i += NT) hbase[i] = make_float2(0.f, 0.f);
    // stage x(t=0)
    for (int i = tid; i < BT * F_; i += NT) {
        int b = i / F_, f = i % F_;
        float v = (b < nb) ? x[((size_t)(b_base + b) * T_) * F_ + f] : 0.0f;
        ((float*)xb[0])[(b >> 1) * F_ * 2 + f * 2 + (b & 1)] = v;
    }
    __syncthreads();

    // Software-pipelined: iteration t runs l0-GEMM(t) and l1-GEMM(t-1) in one
    // phase. Work balance: half0 = l0@NP4 + l1@NP3, half1 = l0@NP3 + l1@NP4
    // (188 vs 176 kg-pairs instead of 208 vs 156).
    int cur = 0;
    for (int t = 0; t < T_; ++t) {
        // ---------- G phase: both layers' GEMMs ----------
        if (half == 0) {
            {
                ull z[4][4];
#pragma unroll
                for (int gt = 0; gt < 4; ++gt)
#pragma unroll
                    for (int p = 0; p < 4; ++p) z[gt][p] = 0ull;
                l0_gemm<4>(sWih0, xb[cur], h0p, z, j, ks);
                store_z<4>(z, z0my, j, 0);
            }
            if (t > 0) {
                ull z3[4][3];
#pragma unroll
                for (int gt = 0; gt < 4; ++gt)
#pragma unroll
                    for (int p = 0; p < 3; ++p) z3[gt][p] = 0ull;
                l1_gemm<3>(h0p + 4 * H_, h1p + 4 * H_, z3, j, ks);
                store_z<3>(z3, z1my, j, 4);
            }
        } else {
            {
                ull z3[4][3];
#pragma unroll
                for (int gt = 0; gt < 4; ++gt)
#pragma unroll
                    for (int p = 0; p < 3; ++p) z3[gt][p] = 0ull;
                l0_gemm<3>(sWih0, xb[cur] + 4 * F_, h0p + 4 * H_, z3, j, ks);
                store_z<3>(z3, z0my, j, 4);
            }
            if (t > 0) {
                ull z[4][4];
#pragma unroll
                for (int gt = 0; gt < 4; ++gt)
#pragma unroll
                    for (int p = 0; p < 4; ++p) z[gt][p] = 0ull;
                l1_gemm<4>(h0p, h1p, z, j, ks);
                store_z<4>(z, z1my, j, 0);
            }
        }
        __syncthreads();

        // ---------- U phase: both gate updates + x staging ----------
        gate_update_layer(z0bu0, z0bu1, sbd0, c0p, h0p, tid);   // h0[t]
        if (t > 0)
            gate_update_layer(z1bu0, z1bu1, sbd1, c1p, h1p, tid); // h1[t-1]
        if (t + 1 < T_) {
            for (int i = tid; i < BT * F_; i += NT) {
                int b = i / F_, f = i % F_;
                float v = (b < nb)
                    ? x[((size_t)(b_base + b) * T_ + (t + 1)) * F_ + f]
                    : 0.0f;
                ((float*)xb[cur ^ 1])[(b >> 1) * F_ * 2 + f * 2 + (b & 1)] = v;
            }
        }
        __syncthreads();
        cur ^= 1;
    }

    // ---------- epilogue: l1 step T-1 (same swapped assignment) ----------
    if (half == 0) {
        ull z3[4][3];
#pragma unroll
        for (int gt = 0; gt < 4; ++gt)
#pragma unroll
            for (int p = 0; p < 3; ++p) z3[gt][p] = 0ull;
        l1_gemm<3>(h0p + 4 * H_, h1p + 4 * H_, z3, j, ks);
        store_z<3>(z3, z1my, j, 4);
    } else {
        ull z[4][4];
#pragma unroll
        for (int gt = 0; gt < 4; ++gt)
#pragma unroll
            for (int p = 0; p < 4; ++p) z[gt][p] = 0ull;
        l1_gemm<4>(h0p, h1p, z, j, ks);
        store_z<4>(z, z1my, j, 0);
    }
    __syncthreads();
    gate_update_layer(z1bu0, z1bu1, sbd1, c1p, h1p, tid);       // h1[T-1]
    __syncthreads();

    // FC head
    if (tid < nb) {
        float s = bfc[0];
#pragma unroll
        for (int k = 0; k < H_; ++k) {
            float2 hv = h1p[(tid >> 1) * H_ + k];
            float h = (tid & 1) ? hv.y : hv.x;
            s = fmaf(h, Wfc[k], s);
        }
        out[b_base + tid] = s;
    }
}

extern "C" void kernel_launch(void* const* d_in, const int* in_sizes, int n_in,
                              void* d_out, int out_size) {
    const float* x    = (const float*)d_in[0];
    const float* Wih0 = (const float*)d_in[1];
    const float* Whh0 = (const float*)d_in[2];
    const float* b0   = (const float*)d_in[3];
    const float* Wih1 = (const float*)d_in[4];
    const float* Whh1 = (const float*)d_in[5];
    const float* b1   = (const float*)d_in[6];
    const float* Wfc  = (const float*)d_in[7];
    const float* bfc  = (const float*)d_in[8];
    float* out = (float*)d_out;
    (void)in_sizes; (void)n_in; (void)out_size;

    prep<<<64, 256>>>(Wih0, Whh0, Wih1, Whh1);

    const int smem_bytes =
        8 * 512 * (int)sizeof(float4) +            // Wih0 cache
        2 * 512 * (int)sizeof(ull) +               // dup'd biases
        4 * P_ * H_ * (int)sizeof(float2) +        // h/c
        4 * 512 * PST * (int)sizeof(ull) +         // zbufs (2 layers x 2 ks)
        2 * P_ * F_ * (int)sizeof(float2);         // x double buffer
    cudaFuncSetAttribute(lstm_persistent,
                         cudaFuncAttributeMaxDynamicSharedMemorySize,
                         smem_bytes);

    lstm_persistent<<<(B_ + BT - 1) / BT, NT, smem_bytes>>>(
        x, b0, b1, Wfc, bfc, out);
}

// round 16
// speedup vs baseline: 1.6392x; 1.1795x over previous
#include <cuda_runtime.h>
#include <math.h>

// Problem constants
#define B_  2048
#define T_  512
#define F_  32
#define H_  128
#define BT  14       // batch rows per CTA -> 147 CTAs = one wave on 148 SMs
#define P_  7        // batch pairs per CTA
#define NT  512      // (half) x (ksplit: lo/hi K) x 128 j
#define PST 7        // zbuf stride in ull per gate row

typedef unsigned long long ull;

// Weights laid out [kg][gt][j] float4 (4 consecutive k per load):
// index = (kg*4 + gt)*128 + j ; gate = gt*128 + j ; k = 4*kg.
// Lanes (consecutive j) are fully coalesced. +2 kg rows pad for prefetch.
__device__ float4 g_Wih0p[(8 + 2) * 512];
__device__ float4 g_Whh0p[(32 + 2) * 512];
__device__ float4 g_Wih1p[(32 + 2) * 512];
__device__ float4 g_Whh1p[(32 + 2) * 512];

__global__ void prep(const float* __restrict__ Wih0,
                     const float* __restrict__ Whh0,
                     const float* __restrict__ Wih1,
                     const float* __restrict__ Whh1) {
    int idx = blockIdx.x * blockDim.x + threadIdx.x;  // 0..16383
    int j = idx & 127, gt = (idx >> 7) & 3, kg = idx >> 9;
    int gate = gt * 128 + j;
    g_Whh0p[idx] = *(const float4*)(Whh0 + gate * 128 + 4 * kg);
    g_Wih1p[idx] = *(const float4*)(Wih1 + gate * 128 + 4 * kg);
    g_Whh1p[idx] = *(const float4*)(Whh1 + gate * 128 + 4 * kg);
    if (kg < 8)
        g_Wih0p[idx] = *(const float4*)(Wih0 + gate * 32 + 4 * kg);
}

__device__ __forceinline__ ull ffma2(ull a, ull b, ull c) {
    ull d;
    asm("fma.rn.f32x2 %0, %1, %2, %3;" : "=l"(d) : "l"(a), "l"(b), "l"(c));
    return d;
}
__device__ __forceinline__ ull addx2(ull a, ull b) {
    ull r;
    asm("add.rn.f32x2 %0, %1, %2;" : "=l"(r) : "l"(a), "l"(b));
    return r;
}
__device__ __forceinline__ ull dup2(float w) {
    ull d;
    asm("mov.b64 %0, {%1, %1};" : "=l"(d) : "f"(w));
    return d;
}
__device__ __forceinline__ float2 u2f(ull v) {
    float2 r;
    asm("mov.b64 {%0, %1}, %2;" : "=f"(r.x), "=f"(r.y) : "l"(v));
    return r;
}
// HW tanh (sm_75+): single MUFU op, max abs err ~1e-5.
__device__ __forceinline__ float tanh_hw(float x) {
    float r;
    asm("tanh.approx.f32 %0, %1;" : "=f"(r) : "f"(x));
    return r;
}
// sigmoid via exact identity sigm(x) = 0.5*tanh(0.5x) + 0.5
__device__ __forceinline__ float sigm(float x) {
    return fmaf(0.5f, tanh_hw(0.5f * x), 0.5f);
}

// 2 k-values, 4 gates, NP pairs. kp = 16B index into each pair's h row.
template <int KDIM, int NP>
__device__ __forceinline__ void k2body(float2 w0, float2 w1, float2 w2, float2 w3,
                                       const float2* __restrict__ hp,
                                       ull z[4][NP], int kp) {
    ull d00 = dup2(w0.x), d01 = dup2(w0.y);
    ull d10 = dup2(w1.x), d11 = dup2(w1.y);
    ull d20 = dup2(w2.x), d21 = dup2(w2.y);
    ull d30 = dup2(w3.x), d31 = dup2(w3.y);
#pragma unroll
    for (int p = 0; p < NP; ++p) {
        ulonglong2 v = ((const ulonglong2*)(hp + p * KDIM))[kp];
        z[0][p] = ffma2(v.y, d01, ffma2(v.x, d00, z[0][p]));
        z[1][p] = ffma2(v.y, d11, ffma2(v.x, d10, z[1][p]));
        z[2][p] = ffma2(v.y, d21, ffma2(v.x, d20, z[2][p]));
        z[3][p] = ffma2(v.y, d31, ffma2(v.x, d30, z[3][p]));
    }
}

// full k-group (4 k) from a float4-per-gate weight vector
template <int KDIM, int NP>
__device__ __forceinline__ void kbody4(const float4 w[4],
                                       const float2* __restrict__ hp,
                                       ull z[4][NP], int kidx) {
    k2body<KDIM, NP>(make_float2(w[0].x, w[0].y), make_float2(w[1].x, w[1].y),
                     make_float2(w[2].x, w[2].y), make_float2(w[3].x, w[3].y),
                     hp, z, 2 * kidx);
    k2body<KDIM, NP>(make_float2(w[0].z, w[0].w), make_float2(w[1].z, w[1].w),
                     make_float2(w[2].z, w[2].w), make_float2(w[3].z, w[3].w),
                     hp, z, 2 * kidx + 1);
}

// Streamed panel: Wt already offset to (kbase row, gt=0, j). Row stride 512
// float4; gt stride 128. Distance-1 rolling prefetch (+2 pad rows exist).
template <int KDIM, int KG, int NP>
__device__ __forceinline__ void panel_g4(const float4* __restrict__ Wt,
                                         const float2* __restrict__ hp,
                                         int kbase, ull z[4][NP]) {
    float4 w0[4];
#pragma unroll
    for (int gt = 0; gt < 4; ++gt) w0[gt] = Wt[gt * 128];
#pragma unroll 1
    for (int kg = 0; kg < KG; ++kg) {
        float4 wn[4];
#pragma unroll
        for (int gt = 0; gt < 4; ++gt) wn[gt] = Wt[(size_t)(kg + 1) * 512 + gt * 128];
        kbody4<KDIM, NP>(w0, hp, z, kbase + kg);
#pragma unroll
        for (int gt = 0; gt < 4; ++gt) w0[gt] = wn[gt];
    }
}

// Cached panel: Ws already offset to j within the cache.
template <int KDIM, int KG, int NP>
__device__ __forceinline__ void panel_s4(const float4* __restrict__ Ws,
                                         const float2* __restrict__ hp,
                                         int kbase, ull z[4][NP]) {
#pragma unroll 1
    for (int kg = 0; kg < KG; ++kg) {
        float4 w[4];
#pragma unroll
        for (int gt = 0; gt < 4; ++gt) w[gt] = Ws[kg * 512 + gt * 128];
        kbody4<KDIM, NP>(w, hp, z, kbase + kg);
    }
}

template <int NP>
__device__ __forceinline__ void l0_gemm(const float4* __restrict__ sWih0,
                                        const float2* __restrict__ xi,
                                        const float2* __restrict__ h0,
                                        ull z[4][NP], int j, int ks) {
    if (ks == 0) {
        panel_s4<F_, 4, NP>(sWih0 + j, xi, 0, z);
        panel_g4<H_, 16, NP>(g_Whh0p + j, h0, 0, z);
    } else {
        panel_s4<F_, 4, NP>(sWih0 + 4 * 512 + j, xi, 4, z);
        panel_g4<H_, 16, NP>(g_Whh0p + 16 * 512 + j, h0, 16, z);
    }
}

template <int NP>
__device__ __forceinline__ void l1_gemm(const float2* __restrict__ h0,
                                        const float2* __restrict__ h1,
                                        ull z[4][NP], int j, int ks) {
    if (ks == 0) {
        panel_g4<H_, 16, NP>(g_Wih1p + j, h0, 0, z);
        panel_g4<H_, 16, NP>(g_Whh1p + j, h1, 0, z);
    } else {
        panel_g4<H_, 16, NP>(g_Wih1p + 16 * 512 + j, h0, 16, z);
        panel_g4<H_, 16, NP>(g_Whh1p + 16 * 512 + j, h1, 16, z);
    }
}

template <int NP>
__device__ __forceinline__ void store_z(ull z[4][NP], ull* __restrict__ zmy,
                                        int j, int pofs) {
#pragma unroll
    for (int gt = 0; gt < 4; ++gt)
#pragma unroll
        for (int p = 0; p < NP; ++p)
            zmy[(gt * 128 + j) * PST + pofs + p] = z[gt][p];
}

// Gate update for one layer: packed-sums the two ksplit partials + dup'd bias,
// applies LSTM nonlinearity (HW tanh), updates c (SMEM) and h (SMEM).
__device__ __forceinline__ void gate_update_layer(const ull* __restrict__ zb0,
                                                  const ull* __restrict__ zb1,
                                                  const ull* __restrict__ sbd,
                                                  float2* __restrict__ cp,
                                                  float2* __restrict__ hp,
                                                  int tid) {
    for (int i = tid; i < P_ * H_; i += NT) {
        int p = i >> 7, j2 = i & 127;
        float2 vi = u2f(addx2(addx2(zb0[(j2      ) * PST + p],
                                    zb1[(j2      ) * PST + p]), sbd[j2]));
        float2 vf = u2f(addx2(addx2(zb0[(j2 + 128) * PST + p],
                                    zb1[(j2 + 128) * PST + p]), sbd[j2 + 128]));
        float2 vg = u2f(addx2(addx2(zb0[(j2 + 256) * PST + p],
                                    zb1[(j2 + 256) * PST + p]), sbd[j2 + 256]));
        float2 vo = u2f(addx2(addx2(zb0[(j2 + 384) * PST + p],
                                    zb1[(j2 + 384) * PST + p]), sbd[j2 + 384]));
        float2 c = cp[p * H_ + j2];
        float2 nc, nh;
        nc.x = sigm(vf.x) * c.x + sigm(vi.x) * tanh_hw(vg.x);
        nc.y = sigm(vf.y) * c.y + sigm(vi.y) * tanh_hw(vg.y);
        nh.x = sigm(vo.x) * tanh_hw(nc.x);
        nh.y = sigm(vo.y) * tanh_hw(nc.y);
        cp[p * H_ + j2] = nc;
        hp[p * H_ + j2] = nh;
    }
}

extern __shared__ float4 smem4[];

__global__ void __launch_bounds__(NT, 1)
lstm_persistent(const float* __restrict__ x,
                const float* __restrict__ b0,
                const float* __restrict__ b1,
                const float* __restrict__ Wfc,
                const float* __restrict__ bfc,
                float* __restrict__ out) {
    // SMEM: [Wih0 8 rows][sbd0,sbd1 dup'd biases][h0,c0,h1,c1][z0 x2][z1 x2][x x2]
    float4* sWih0 = smem4;                            // 8*512 f4 = 64KB
    ull* sbd0 = (ull*)(smem4 + 8 * 512);              // 512 ull
    ull* sbd1 = sbd0 + 512;                           // 512 ull
    float2* hbase = (float2*)(sbd1 + 512);
    float2* h0p = hbase;                 // P_*H_
    float2* c0p = h0p + P_ * H_;
    float2* h1p = c0p + P_ * H_;
    float2* c1p = h1p + P_ * H_;
    ull* z0bu0 = (ull*)(c1p + P_ * H_);  // 512*PST each
    ull* z0bu1 = z0bu0 + 512 * PST;
    ull* z1bu0 = z0bu1 + 512 * PST;
    ull* z1bu1 = z1bu0 + 512 * PST;
    float2* xb[2] = { (float2*)(z1bu1 + 512 * PST),
                      (float2*)(z1bu1 + 512 * PST) + P_ * F_ };

    const int tid = threadIdx.x;
    const int j = tid & 127;             // output index
    const int ks = (tid >> 7) & 1;       // k-split
    const int half = tid >> 8;           // batch-pair half (swapped per layer)
    const int b_base = blockIdx.x * BT;
    const int nb = min(BT, B_ - b_base);
    ull* z0my = ks ? z0bu1 : z0bu0;
    ull* z1my = ks ? z1bu1 : z1bu0;

    // fill weight cache + dup'd biases (once per launch)
    for (int i = tid; i < 8 * 512; i += NT) sWih0[i] = g_Wih0p[i];
    if (tid < 512) { sbd0[tid] = dup2(b0[tid]); sbd1[tid] = dup2(b1[tid]); }
    // zero h/c
    for (int i = tid; i < 4 * P_ * H_; i += NT) hbase[i] = make_float2(0.f, 0.f);
    // stage x(t=0)
    for (int i = tid; i < BT * F_; i += NT) {
        int b = i / F_, f = i % F_;
        float v = (b < nb) ? x[((size_t)(b_base + b) * T_) * F_ + f] : 0.0f;
        ((float*)xb[0])[(b >> 1) * F_ * 2 + f * 2 + (b & 1)] = v;
    }
    __syncthreads();

    // Software-pipelined: iteration t runs l0-GEMM(t) and l1-GEMM(t-1) in one
    // phase. Work balance: half0 = l0@NP4 + l1@NP3, half1 = l0@NP3 + l1@NP4.
    int cur = 0;
    for (int t = 0; t < T_; ++t) {
        // ---------- G phase: both layers' GEMMs ----------
        if (half == 0) {
            {
                ull z[4][4];
#pragma unroll
                for (int gt = 0; gt < 4; ++gt)
#pragma unroll
                    for (int p = 0; p < 4; ++p) z[gt][p] = 0ull;
                l0_gemm<4>(sWih0, xb[cur], h0p, z, j, ks);
                store_z<4>(z, z0my, j, 0);
            }
            if (t > 0) {
                ull z3[4][3];
#pragma unroll
                for (int gt = 0; gt < 4; ++gt)
#pragma unroll
                    for (int p = 0; p < 3; ++p) z3[gt][p] = 0ull;
                l1_gemm<3>(h0p + 4 * H_, h1p + 4 * H_, z3, j, ks);
                store_z<3>(z3, z1my, j, 4);
            }
        } else {
            {
                ull z3[4][3];
#pragma unroll
                for (int gt = 0; gt < 4; ++gt)
#pragma unroll
                    for (int p = 0; p < 3; ++p) z3[gt][p] = 0ull;
                l0_gemm<3>(sWih0, xb[cur] + 4 * F_, h0p + 4 * H_, z3, j, ks);
                store_z<3>(z3, z0my, j, 4);
            }
            if (t > 0) {
                ull z[4][4];
#pragma unroll
                for (int gt = 0; gt < 4; ++gt)
#pragma unroll
                    for (int p = 0; p < 4; ++p) z[gt][p] = 0ull;
                l1_gemm<4>(h0p, h1p, z, j, ks);
                store_z<4>(z, z1my, j, 0);
            }
        }
        __syncthreads();

        // ---------- U phase: both gate updates + x staging ----------
        gate_update_layer(z0bu0, z0bu1, sbd0, c0p, h0p, tid);   // h0[t]
        if (t > 0)
            gate_update_layer(z1bu0, z1bu1, sbd1, c1p, h1p, tid); // h1[t-1]
        if (t + 1 < T_) {
            for (int i = tid; i < BT * F_; i += NT) {
                int b = i / F_, f = i % F_;
                float v = (b < nb)
                    ? x[((size_t)(b_base + b) * T_ + (t + 1)) * F_ + f]
                    : 0.0f;
                ((float*)xb[cur ^ 1])[(b >> 1) * F_ * 2 + f * 2 + (b & 1)] = v;
            }
        }
        __syncthreads();
        cur ^= 1;
    }

    // ---------- epilogue: l1 step T-1 (same swapped assignment) ----------
    if (half == 0) {
        ull z3[4][3];
#pragma unroll
        for (int gt = 0; gt < 4; ++gt)
#pragma unroll
            for (int p = 0; p < 3; ++p) z3[gt][p] = 0ull;
        l1_gemm<3>(h0p + 4 * H_, h1p + 4 * H_, z3, j, ks);
        store_z<3>(z3, z1my, j, 4);
    } else {
        ull z[4][4];
#pragma unroll
        for (int gt = 0; gt < 4; ++gt)
#pragma unroll
            for (int p = 0; p < 4; ++p) z[gt][p] = 0ull;
        l1_gemm<4>(h0p, h1p, z, j, ks);
        store_z<4>(z, z1my, j, 0);
    }
    __syncthreads();
    gate_update_layer(z1bu0, z1bu1, sbd1, c1p, h1p, tid);       // h1[T-1]
    __syncthreads();

    // FC head
    if (tid < nb) {
        float s = bfc[0];
#pragma unroll
        for (int k = 0; k < H_; ++k) {
            float2 hv = h1p[(tid >> 1) * H_ + k];
            float h = (tid & 1) ? hv.y : hv.x;
            s = fmaf(h, Wfc[k], s);
        }
        out[b_base + tid] = s;
    }
}

extern "C" void kernel_launch(void* const* d_in, const int* in_sizes, int n_in,
                              void* d_out, int out_size) {
    const float* x    = (const float*)d_in[0];
    const float* Wih0 = (const float*)d_in[1];
    const float* Whh0 = (const float*)d_in[2];
    const float* b0   = (const float*)d_in[3];
    const float* Wih1 = (const float*)d_in[4];
    const float* Whh1 = (const float*)d_in[5];
    const float* b1   = (const float*)d_in[6];
    const float* Wfc  = (const float*)d_in[7];
    const float* bfc  = (const float*)d_in[8];
    float* out = (float*)d_out;
    (void)in_sizes; (void)n_in; (void)out_size;

    prep<<<64, 256>>>(Wih0, Whh0, Wih1, Whh1);

    const int smem_bytes =
        8 * 512 * (int)sizeof(float4) +            // Wih0 cache
        2 * 512 * (int)sizeof(ull) +               // dup'd biases
        4 * P_ * H_ * (int)sizeof(float2) +        // h/c
        4 * 512 * PST * (int)sizeof(ull) +         // zbufs (2 layers x 2 ks)
        2 * P_ * F_ * (int)sizeof(float2);         // x double buffer
    cudaFuncSetAttribute(lstm_persistent,
                         cudaFuncAttributeMaxDynamicSharedMemorySize,
                         smem_bytes);

    lstm_persistent<<<(B_ + BT - 1) / BT, NT, smem_bytes>>>(
        x, b0, b1, Wfc, bfc, out);
}

// round 17
// speedup vs baseline: 1.6549x; 1.0096x over previous
#include <cuda_runtime.h>
#include <math.h>

// Problem constants
#define B_  2048
#define T_  512
#define F_  32
#define H_  128
#define BT  14       // batch rows per CTA -> 147 CTAs = one wave on 148 SMs
#define P_  7        // batch pairs per CTA
#define NT  512      // (half) x (ksplit) x 128 j
#define PS  512      // transposed zbuf stride per pair (ull): conflict-free

typedef unsigned long long ull;

// Weights laid out [kg][gt][j] float4 (4 consecutive k per load):
// index = (kg*4 + gt)*128 + j ; gate = gt*128 + j ; k = 4*kg.
// Lanes (consecutive j) are fully coalesced. +2 kg rows pad for prefetch.
__device__ float4 g_Wih0p[(8 + 2) * 512];
__device__ float4 g_Whh0p[(32 + 2) * 512];
__device__ float4 g_Wih1p[(32 + 2) * 512];
__device__ float4 g_Whh1p[(32 + 2) * 512];

__global__ void prep(const float* __restrict__ Wih0,
                     const float* __restrict__ Whh0,
                     const float* __restrict__ Wih1,
                     const float* __restrict__ Whh1) {
    int idx = blockIdx.x * blockDim.x + threadIdx.x;  // 0..16383
    int j = idx & 127, gt = (idx >> 7) & 3, kg = idx >> 9;
    int gate = gt * 128 + j;
    g_Whh0p[idx] = *(const float4*)(Whh0 + gate * 128 + 4 * kg);
    g_Wih1p[idx] = *(const float4*)(Wih1 + gate * 128 + 4 * kg);
    g_Whh1p[idx] = *(const float4*)(Whh1 + gate * 128 + 4 * kg);
    if (kg < 8)
        g_Wih0p[idx] = *(const float4*)(Wih0 + gate * 32 + 4 * kg);
}

__device__ __forceinline__ ull ffma2(ull a, ull b, ull c) {
    ull d;
    asm("fma.rn.f32x2 %0, %1, %2, %3;" : "=l"(d) : "l"(a), "l"(b), "l"(c));
    return d;
}
__device__ __forceinline__ ull addx2(ull a, ull b) {
    ull r;
    asm("add.rn.f32x2 %0, %1, %2;" : "=l"(r) : "l"(a), "l"(b));
    return r;
}
__device__ __forceinline__ ull dup2(float w) {
    ull d;
    asm("mov.b64 %0, {%1, %1};" : "=l"(d) : "f"(w));
    return d;
}
__device__ __forceinline__ float2 u2f(ull v) {
    float2 r;
    asm("mov.b64 {%0, %1}, %2;" : "=f"(r.x), "=f"(r.y) : "l"(v));
    return r;
}
// HW tanh (sm_75+): single MUFU op, max abs err ~1e-5.
__device__ __forceinline__ float tanh_hw(float x) {
    float r;
    asm("tanh.approx.f32 %0, %1;" : "=f"(r) : "f"(x));
    return r;
}
// sigmoid via exact identity sigm(x) = 0.5*tanh(0.5x) + 0.5
__device__ __forceinline__ float sigm(float x) {
    return fmaf(0.5f, tanh_hw(0.5f * x), 0.5f);
}

// 2 k-values, 4 gates, NP pairs. kp = 16B index into each pair's h row.
template <int KDIM, int NP>
__device__ __forceinline__ void k2body(float2 w0, float2 w1, float2 w2, float2 w3,
                                       const float2* __restrict__ hp,
                                       ull z[4][4], int kp) {
    ull d00 = dup2(w0.x), d01 = dup2(w0.y);
    ull d10 = dup2(w1.x), d11 = dup2(w1.y);
    ull d20 = dup2(w2.x), d21 = dup2(w2.y);
    ull d30 = dup2(w3.x), d31 = dup2(w3.y);
#pragma unroll
    for (int p = 0; p < NP; ++p) {
        ulonglong2 v = ((const ulonglong2*)(hp + p * KDIM))[kp];
        z[0][p] = ffma2(v.y, d01, ffma2(v.x, d00, z[0][p]));
        z[1][p] = ffma2(v.y, d11, ffma2(v.x, d10, z[1][p]));
        z[2][p] = ffma2(v.y, d21, ffma2(v.x, d20, z[2][p]));
        z[3][p] = ffma2(v.y, d31, ffma2(v.x, d30, z[3][p]));
    }
}

// full k-group (4 k) from a float4-per-gate weight vector
template <int KDIM, int NP>
__device__ __forceinline__ void kbody4(const float4 w[4],
                                       const float2* __restrict__ hp,
                                       ull z[4][4], int kidx) {
    k2body<KDIM, NP>(make_float2(w[0].x, w[0].y), make_float2(w[1].x, w[1].y),
                     make_float2(w[2].x, w[2].y), make_float2(w[3].x, w[3].y),
                     hp, z, 2 * kidx);
    k2body<KDIM, NP>(make_float2(w[0].z, w[0].w), make_float2(w[1].z, w[1].w),
                     make_float2(w[2].z, w[2].w), make_float2(w[3].z, w[3].w),
                     hp, z, 2 * kidx + 1);
}

// Streamed panel: Wt already offset to (kbase row, gt=0, j). Row stride 512
// float4; gt stride 128. Distance-1 rolling prefetch (+2 pad rows exist).
template <int KDIM, int KG, int NP>
__device__ __forceinline__ void panel_g4(const float4* __restrict__ Wt,
                                         const float2* __restrict__ hp,
                                         int kbase, ull z[4][4]) {
    float4 w0[4];
#pragma unroll
    for (int gt = 0; gt < 4; ++gt) w0[gt] = Wt[gt * 128];
#pragma unroll 1
    for (int kg = 0; kg < KG; ++kg) {
        float4 wn[4];
#pragma unroll
        for (int gt = 0; gt < 4; ++gt) wn[gt] = Wt[(size_t)(kg + 1) * 512 + gt * 128];
        kbody4<KDIM, NP>(w0, hp, z, kbase + kg);
#pragma unroll
        for (int gt = 0; gt < 4; ++gt) w0[gt] = wn[gt];
    }
}

// Cached panel: Ws already offset to j within the cache.
template <int KDIM, int KG, int NP>
__device__ __forceinline__ void panel_s4(const float4* __restrict__ Ws,
                                         const float2* __restrict__ hp,
                                         int kbase, ull z[4][4]) {
#pragma unroll 1
    for (int kg = 0; kg < KG; ++kg) {
        float4 w[4];
#pragma unroll
        for (int gt = 0; gt < 4; ++gt) w[gt] = Ws[kg * 512 + gt * 128];
        kbody4<KDIM, NP>(w, hp, z, kbase + kg);
    }
}

template <int NP>
__device__ __forceinline__ void l0_gemm(const float4* __restrict__ sWih0,
                                        const float2* __restrict__ xi,
                                        const float2* __restrict__ h0,
                                        ull z[4][4], int j, int ks) {
    if (ks == 0) {
        panel_s4<F_, 4, NP>(sWih0 + j, xi, 0, z);
        panel_g4<H_, 16, NP>(g_Whh0p + j, h0, 0, z);
    } else {
        panel_s4<F_, 4, NP>(sWih0 + 4 * 512 + j, xi, 4, z);
        panel_g4<H_, 16, NP>(g_Whh0p + 16 * 512 + j, h0, 16, z);
    }
}

template <int NP>
__device__ __forceinline__ void l1_gemm(const float2* __restrict__ h0,
                                        const float2* __restrict__ h1,
                                        ull z[4][4], int j, int ks) {
    if (ks == 0) {
        panel_g4<H_, 16, NP>(g_Wih1p + j, h0, 0, z);
        panel_g4<H_, 16, NP>(g_Whh1p + j, h1, 0, z);
    } else {
        panel_g4<H_, 16, NP>(g_Wih1p + 16 * 512 + j, h0, 16, z);
        panel_g4<H_, 16, NP>(g_Whh1p + 16 * 512 + j, h1, 16, z);
    }
}

// Transposed zbuf store: zb[(pofs+p)*PS + gt*128 + j]  (conflict-free)
template <int NP>
__device__ __forceinline__ void store_zt(ull z[4][4], ull* __restrict__ zb,
                                         int j, int pofs) {
#pragma unroll
    for (int gt = 0; gt < 4; ++gt)
#pragma unroll
        for (int p = 0; p < NP; ++p)
            zb[(pofs + p) * PS + gt * 128 + j] = z[gt][p];
}

// l0 gate update from in-register ks0 partial + ks1 partial in zbuf.
template <int NP, int POFS>
__device__ __forceinline__ void l0_update(ull zr[4][4],
                                          const ull* __restrict__ z0b,
                                          const ull* __restrict__ sbd0,
                                          float2* __restrict__ c0p,
                                          float2* __restrict__ h0p, int j) {
#pragma unroll
    for (int p = 0; p < NP; ++p) {
        int pp = POFS + p;
        float2 vi = u2f(addx2(addx2(zr[0][p], z0b[pp * PS + j]),
                              sbd0[j]));
        float2 vf = u2f(addx2(addx2(zr[1][p], z0b[pp * PS + 128 + j]),
                              sbd0[128 + j]));
        float2 vg = u2f(addx2(addx2(zr[2][p], z0b[pp * PS + 256 + j]),
                              sbd0[256 + j]));
        float2 vo = u2f(addx2(addx2(zr[3][p], z0b[pp * PS + 384 + j]),
                              sbd0[384 + j]));
        float2 c = c0p[pp * H_ + j];
        float2 nc, nh;
        nc.x = sigm(vf.x) * c.x + sigm(vi.x) * tanh_hw(vg.x);
        nc.y = sigm(vf.y) * c.y + sigm(vi.y) * tanh_hw(vg.y);
        nh.x = sigm(vo.x) * tanh_hw(nc.x);
        nh.y = sigm(vo.y) * tanh_hw(nc.y);
        c0p[pp * H_ + j] = nc;
        h0p[pp * H_ + j] = nh;
    }
}

// l1 gate update: items lin, lin+256, ... over 896; both partials from zbuf.
__device__ __forceinline__ void l1_update(const ull* __restrict__ z1b0,
                                          const ull* __restrict__ z1b1,
                                          const ull* __restrict__ sbd1,
                                          float2* __restrict__ c1p,
                                          float2* __restrict__ h1p, int lin) {
    for (int it = lin; it < P_ * H_; it += 256) {
        int p = it >> 7, j2 = it & 127;
        float2 vi = u2f(addx2(addx2(z1b0[p * PS + j2],
                                    z1b1[p * PS + j2]), sbd1[j2]));
        float2 vf = u2f(addx2(addx2(z1b0[p * PS + 128 + j2],
                                    z1b1[p * PS + 128 + j2]), sbd1[128 + j2]));
        float2 vg = u2f(addx2(addx2(z1b0[p * PS + 256 + j2],
                                    z1b1[p * PS + 256 + j2]), sbd1[256 + j2]));
        float2 vo = u2f(addx2(addx2(z1b0[p * PS + 384 + j2],
                                    z1b1[p * PS + 384 + j2]), sbd1[384 + j2]));
        float2 c = c1p[p * H_ + j2];
        float2 nc, nh;
        nc.x = sigm(vf.x) * c.x + sigm(vi.x) * tanh_hw(vg.x);
        nc.y = sigm(vf.y) * c.y + sigm(vi.y) * tanh_hw(vg.y);
        nh.x = sigm(vo.x) * tanh_hw(nc.x);
        nh.y = sigm(vo.y) * tanh_hw(nc.y);
        c1p[p * H_ + j2] = nc;
        h1p[p * H_ + j2] = nh;
    }
}

extern __shared__ float4 smem4[];

__global__ void __launch_bounds__(NT, 1)
lstm_persistent(const float* __restrict__ x,
                const float* __restrict__ b0,
                const float* __restrict__ b1,
                const float* __restrict__ Wfc,
                const float* __restrict__ bfc,
                float* __restrict__ out) {
    // SMEM: [Wih0 8 rows][sbd0,sbd1][h0,c0,h1,c1][z0b][z1b x2][x x2]
    float4* sWih0 = smem4;                            // 8*512 f4 = 64KB
    ull* sbd0 = (ull*)(smem4 + 8 * 512);              // 512 ull
    ull* sbd1 = sbd0 + 512;                           // 512 ull
    float2* hbase = (float2*)(sbd1 + 512);
    float2* h0p = hbase;                 // P_*H_
    float2* c0p = h0p + P_ * H_;
    float2* h1p = c0p + P_ * H_;
    float2* c1p = h1p + P_ * H_;
    ull* z0b  = (ull*)(c1p + P_ * H_);   // P_*PS (ks1 partial only)
    ull* z1b0 = z0b + P_ * PS;           // P_*PS (l1 ks0 partial)
    ull* z1b1 = z1b0 + P_ * PS;          // P_*PS (l1 ks1 partial)
    float2* xb[2] = { (float2*)(z1b1 + P_ * PS),
                      (float2*)(z1b1 + P_ * PS) + P_ * F_ };

    const int tid = threadIdx.x;
    const int j = tid & 127;             // output index
    const int ks = (tid >> 7) & 1;       // k-split
    const int half = tid >> 8;           // batch-pair half (swapped per layer)
    const int b_base = blockIdx.x * BT;
    const int nb = min(BT, B_ - b_base);
    ull* z1my = ks ? z1b1 : z1b0;
    const int lin = half * 128 + j;      // l1-update item base for ks1 threads

    // fill weight cache + dup'd biases (once per launch)
    for (int i = tid; i < 8 * 512; i += NT) sWih0[i] = g_Wih0p[i];
    if (tid < 512) { sbd0[tid] = dup2(b0[tid]); sbd1[tid] = dup2(b1[tid]); }
    // zero h/c
    for (int i = tid; i < 4 * P_ * H_; i += NT) hbase[i] = make_float2(0.f, 0.f);
    // stage x(t=0)
    for (int i = tid; i < BT * F_; i += NT) {
        int b = i / F_, f = i % F_;
        float v = (b < nb) ? x[((size_t)(b_base + b) * T_) * F_ + f] : 0.0f;
        ((float*)xb[0])[(b >> 1) * F_ * 2 + f * 2 + (b & 1)] = v;
    }
    __syncthreads();

    // Software-pipelined: step t runs l1-GEMM(t-1) then l0-GEMM(t) in one
    // phase. ks0 threads KEEP their l0 partial in registers across the
    // barrier (their regs exactly cover all l0 items); only ks1's l0 partial
    // goes through SMEM. l1 partials both go through SMEM; ks1 threads do
    // the l1 updates. Pair-swap balance: l0 half0@NP4/half1@NP3, l1 swapped.
    int cur = 0;
    for (int t = 0; t < T_; ++t) {
        ull z0r[4][4];
        // ---------- G phase ----------
        if (t > 0) {            // l1 GEMM for step t-1
            ull z[4][4];
            if (half == 0) {
#pragma unroll
                for (int gt = 0; gt < 4; ++gt)
#pragma unroll
                    for (int p = 0; p < 3; ++p) z[gt][p] = 0ull;
                l1_gemm<3>(h0p + 4 * H_, h1p + 4 * H_, z, j, ks);
                store_zt<3>(z, z1my, j, 4);
            } else {
#pragma unroll
                for (int gt = 0; gt < 4; ++gt)
#pragma unroll
                    for (int p = 0; p < 4; ++p) z[gt][p] = 0ull;
                l1_gemm<4>(h0p, h1p, z, j, ks);
                store_zt<4>(z, z1my, j, 0);
            }
        }
        if (half == 0) {        // l0 GEMM for step t
#pragma unroll
            for (int gt = 0; gt < 4; ++gt)
#pragma unroll
                for (int p = 0; p < 4; ++p) z0r[gt][p] = 0ull;
            l0_gemm<4>(sWih0, xb[cur], h0p, z0r, j, ks);
            if (ks) store_zt<4>(z0r, z0b, j, 0);
        } else {
#pragma unroll
            for (int gt = 0; gt < 4; ++gt)
#pragma unroll
                for (int p = 0; p < 3; ++p) z0r[gt][p] = 0ull;
            l0_gemm<3>(sWih0, xb[cur] + 4 * F_, h0p + 4 * H_, z0r, j, ks);
            if (ks) store_zt<3>(z0r, z0b, j, 4);
        }
        __syncthreads();

        // ---------- U phase ----------
        if (ks == 0) {
            if (half == 0) l0_update<4, 0>(z0r, z0b, sbd0, c0p, h0p, j);
            else           l0_update<3, 4>(z0r, z0b, sbd0, c0p, h0p, j);
        } else if (t > 0) {
            l1_update(z1b0, z1b1, sbd1, c1p, h1p, lin);
        }
        if (t + 1 < T_) {
            for (int i = tid; i < BT * F_; i += NT) {
                int b = i / F_, f = i % F_;
                float v = (b < nb)
                    ? x[((size_t)(b_base + b) * T_ + (t + 1)) * F_ + f]
                    : 0.0f;
                ((float*)xb[cur ^ 1])[(b >> 1) * F_ * 2 + f * 2 + (b & 1)] = v;
            }
        }
        __syncthreads();
        cur ^= 1;
    }

    // ---------- epilogue: l1 step T-1 ----------
    {
        ull z[4][4];
        if (half == 0) {
#pragma unroll
            for (int gt = 0; gt < 4; ++gt)
#pragma unroll
                for (int p = 0; p < 3; ++p) z[gt][p] = 0ull;
            l1_gemm<3>(h0p + 4 * H_, h1p + 4 * H_, z, j, ks);
            store_zt<3>(z, z1my, j, 4);
        } else {
#pragma unroll
            for (int gt = 0; gt < 4; ++gt)
#pragma unroll
                for (int p = 0; p < 4; ++p) z[gt][p] = 0ull;
            l1_gemm<4>(h0p, h1p, z, j, ks);
            store_zt<4>(z, z1my, j, 0);
        }
    }
    __syncthreads();
    if (ks == 1) l1_update(z1b0, z1b1, sbd1, c1p, h1p, lin);
    __syncthreads();

    // FC head
    if (tid < nb) {
        float s = bfc[0];
#pragma unroll
        for (int k = 0; k < H_; ++k) {
            float2 hv = h1p[(tid >> 1) * H_ + k];
            float h = (tid & 1) ? hv.y : hv.x;
            s = fmaf(h, Wfc[k], s);
        }
        out[b_base + tid] = s;
    }
}

extern "C" void kernel_launch(void* const* d_in, const int* in_sizes, int n_in,
                              void* d_out, int out_size) {
    const float* x    = (const float*)d_in[0];
    const float* Wih0 = (const float*)d_in[1];
    const float* Whh0 = (const float*)d_in[2];
    const float* b0   = (const float*)d_in[3];
    const float* Wih1 = (const float*)d_in[4];
    const float* Whh1 = (const float*)d_in[5];
    const float* b1   = (const float*)d_in[6];
    const float* Wfc  = (const float*)d_in[7];
    const float* bfc  = (const float*)d_in[8];
    float* out = (float*)d_out;
    (void)in_sizes; (void)n_in; (void)out_size;

    prep<<<64, 256>>>(Wih0, Whh0, Wih1, Whh1);

    const int smem_bytes =
        8 * 512 * (int)sizeof(float4) +            // Wih0 cache
        2 * 512 * (int)sizeof(ull) +               // dup'd biases
        4 * P_ * H_ * (int)sizeof(float2) +        // h/c
        3 * P_ * PS * (int)sizeof(ull) +           // zbufs (z0 ks1, z1 x2)
        2 * P_ * F_ * (int)sizeof(float2);         // x double buffer
    cudaFuncSetAttribute(lstm_persistent,
                         cudaFuncAttributeMaxDynamicSharedMemorySize,
                         smem_bytes);

    lstm_persistent<<<(B_ + BT - 1) / BT, NT, smem_bytes>>>(
        x, b0, b1, Wfc, bfc, out);
}